// round 4
// baseline (speedup 1.0000x reference)
#include <cuda_runtime.h>
#include <cuda_bf16.h>
#include <cstdint>

#define NLAYERS 4
#define HID 512
#define BATCH 32
#define SEQ 2048
#define MTOT (BATCH*SEQ)          // 65536
#define NC 16                     // scan chunks
#define TC (SEQ/NC)               // 128 steps per chunk

// ---------------- GEMM tiling ----------------
#define BM 128
#define BN 128
#define BK 32
#define LDA 40                    // BK + 8 pad (row = 80B)
#define LDB 136                   // BN + 8 pad (row = 272B)
#define STAGE_EL (2*BM*LDA + 2*BK*LDB)            // 18944 bf16
#define SMEM_BYTES (2*STAGE_EL*2)                 // 75776 bytes

// ---------------- scratch ----------------
__device__ float g_k[(size_t)MTOT * HID];
__device__ float g_p[(size_t)MTOT * HID];
__device__ __nv_bfloat16 g_Ah[(size_t)MTOT * HID];
__device__ __nv_bfloat16 g_Al[(size_t)MTOT * HID];
__device__ __nv_bfloat16 g_Wsp_hi[(size_t)NLAYERS * 2 * HID * HID];
__device__ __nv_bfloat16 g_Wsp_lo[(size_t)NLAYERS * 2 * HID * HID];
__device__ float g_cA[BATCH * NC * HID];
__device__ float g_cB[BATCH * NC * HID];
__device__ float g_hin[BATCH * NC * HID];

// ---------------- helpers ----------------
__device__ __forceinline__ uint32_t saddr(const void* p) {
    return (uint32_t)__cvta_generic_to_shared(p);
}
__device__ __forceinline__ void cpasync16(void* smem, const void* g) {
    asm volatile("cp.async.cg.shared.global [%0], [%1], 16;"
                 :: "r"(saddr(smem)), "l"(g));
}
__device__ __forceinline__ void cp_commit() {
    asm volatile("cp.async.commit_group;");
}
__device__ __forceinline__ void cp_wait0() {
    asm volatile("cp.async.wait_group 0;");
}
__device__ __forceinline__ void ldm_x4(uint32_t* r, uint32_t a) {
    asm volatile("ldmatrix.sync.aligned.m8n8.x4.shared.b16 {%0,%1,%2,%3}, [%4];"
                 : "=r"(r[0]), "=r"(r[1]), "=r"(r[2]), "=r"(r[3]) : "r"(a));
}
__device__ __forceinline__ void ldm_x2t(uint32_t* r, uint32_t a) {
    asm volatile("ldmatrix.sync.aligned.m8n8.x2.trans.shared.b16 {%0,%1}, [%2];"
                 : "=r"(r[0]), "=r"(r[1]) : "r"(a));
}
__device__ __forceinline__ void mma16816(float* c, const uint32_t* a, const uint32_t* b) {
    asm volatile(
        "mma.sync.aligned.m16n8k16.row.col.f32.bf16.bf16.f32 "
        "{%0,%1,%2,%3}, {%4,%5,%6,%7}, {%8,%9}, {%0,%1,%2,%3};"
        : "+f"(c[0]), "+f"(c[1]), "+f"(c[2]), "+f"(c[3])
        : "r"(a[0]), "r"(a[1]), "r"(a[2]), "r"(a[3]), "r"(b[0]), "r"(b[1]));
}
__device__ __forceinline__ void split2(float x, float y,
                                       __nv_bfloat16* hp, __nv_bfloat16* lp) {
    __nv_bfloat16 hx = __float2bfloat16(x);
    __nv_bfloat16 hy = __float2bfloat16(y);
    __nv_bfloat16 lx = __float2bfloat16(x - __bfloat162float(hx));
    __nv_bfloat16 ly = __float2bfloat16(y - __bfloat162float(hy));
    *reinterpret_cast<__nv_bfloat162*>(hp) = __halves2bfloat162(hx, hy);
    *reinterpret_cast<__nv_bfloat162*>(lp) = __halves2bfloat162(lx, ly);
}

// ============================================================================
// One-shot conversion kernels
// ============================================================================
__global__ void __launch_bounds__(256) split_w(const float* __restrict__ Wz,
                                               const float* __restrict__ Wh) {
    size_t i = (size_t)blockIdx.x * 256 + threadIdx.x;    // over 4*512*512
    size_t l = i >> 18, r = i & ((1u << 18) - 1);
    float z = Wz[i], h = Wh[i];
    {
        size_t o = ((l * 2 + 0) << 18) + r;
        __nv_bfloat16 hi = __float2bfloat16(z);
        g_Wsp_hi[o] = hi;
        g_Wsp_lo[o] = __float2bfloat16(z - __bfloat162float(hi));
    }
    {
        size_t o = ((l * 2 + 1) << 18) + r;
        __nv_bfloat16 hi = __float2bfloat16(h);
        g_Wsp_hi[o] = hi;
        g_Wsp_lo[o] = __float2bfloat16(h - __bfloat162float(hi));
    }
}

__global__ void __launch_bounds__(256) split_x(const float* __restrict__ x) {
    size_t i = (size_t)blockIdx.x * 256 + threadIdx.x;    // over MTOT*HID/2
    float2 v = ((const float2*)x)[i];
    split2(v.x, v.y, g_Ah + 2 * i, g_Al + 2 * i);
}

// ============================================================================
// Fused dual GEMM (bf16x3): reads pre-split bf16 A and W via cp.async.
// grid = (8, MTOT/128): blockIdx.x = {4 n-tiles} x {z / h}.
// ============================================================================
__global__ void __launch_bounds__(256, 2) gates_gemm(
    int layer, const float* __restrict__ bz, const float* __restrict__ bh)
{
    extern __shared__ __align__(16) char smem_raw[];
    __nv_bfloat16* s = (__nv_bfloat16*)smem_raw;

    const int tid  = threadIdx.x;
    const int lane = tid & 31;
    const int warp = tid >> 5;
    const int wm   = warp >> 2;
    const int wn   = warp & 3;
    const int zsel = blockIdx.x >> 2;
    const int colBase = (blockIdx.x & 3) * BN;
    const size_t rowBase = (size_t)blockIdx.y * BM;

    const __nv_bfloat16* Wh_ = g_Wsp_hi + (((size_t)layer * 2 + zsel) << 18);
    const __nv_bfloat16* Wl_ = g_Wsp_lo + (((size_t)layer * 2 + zsel) << 18);
    const float* bias = zsel ? bh : bz;
    float*       Out  = zsel ? g_p : g_k;

    auto issue = [&](int kt, int st) {
        __nv_bfloat16* sb = s + st * STAGE_EL;
#pragma unroll
        for (int j = 0; j < 4; ++j) {                  // A: 1024 16B chunks
            int i = tid + 256 * j;
            int row = i >> 3, rem = i & 7, hl = rem >> 2, ch = rem & 3;
            const __nv_bfloat16* gsrc = (hl ? g_Al : g_Ah)
                + (rowBase + row) * HID + kt * BK + ch * 8;
            cpasync16(sb + hl * (BM * LDA) + row * LDA + ch * 8, gsrc);
        }
#pragma unroll
        for (int j = 0; j < 4; ++j) {                  // B: 1024 16B chunks
            int i = tid + 256 * j;
            int row = i >> 5, rem = i & 31, hl = rem >> 4, ch = rem & 15;
            const __nv_bfloat16* gsrc = (hl ? Wl_ : Wh_)
                + (size_t)(kt * BK + row) * HID + colBase + ch * 8;
            cpasync16(sb + 2 * BM * LDA + hl * (BK * LDB) + row * LDB + ch * 8, gsrc);
        }
        cp_commit();
    };

    float acc[4][4][4];
#pragma unroll
    for (int mt = 0; mt < 4; ++mt)
#pragma unroll
        for (int nt = 0; nt < 4; ++nt)
#pragma unroll
            for (int r = 0; r < 4; ++r) acc[mt][nt][r] = 0.f;

    auto comp = [&](int st) {
        const __nv_bfloat16* sAh = s + st * STAGE_EL;
        const __nv_bfloat16* sAl = sAh + BM * LDA;
        const __nv_bfloat16* sBh = sAh + 2 * BM * LDA;
        const __nv_bfloat16* sBl = sBh + BK * LDB;
#pragma unroll
        for (int ks = 0; ks < 2; ++ks) {
            uint32_t Bh[4][2], Bl[4][2];
#pragma unroll
            for (int nt = 0; nt < 4; ++nt) {
                int br = ks * 16 + (lane & 15);
                int bc = wn * 32 + nt * 8;
                ldm_x2t(Bh[nt], saddr(sBh + br * LDB + bc));
                ldm_x2t(Bl[nt], saddr(sBl + br * LDB + bc));
            }
#pragma unroll
            for (int mt = 0; mt < 4; ++mt) {
                uint32_t Ah[4], Al[4];
                int ar = wm * 64 + mt * 16 + (lane & 15);
                int ac = ks * 16 + ((lane >> 4) << 3);
                ldm_x4(Ah, saddr(sAh + ar * LDA + ac));
                ldm_x4(Al, saddr(sAl + ar * LDA + ac));
#pragma unroll
                for (int nt = 0; nt < 4; ++nt) {
                    mma16816(acc[mt][nt], Ah, Bh[nt]);
                    mma16816(acc[mt][nt], Ah, Bl[nt]);
                    mma16816(acc[mt][nt], Al, Bh[nt]);
                }
            }
        }
    };

    issue(0, 0);
    const int KI = HID / BK;    // 16
    for (int kt = 0; kt < KI; ++kt) {
        int st = kt & 1;
        cp_wait0();
        __syncthreads();
        if (kt + 1 < KI) issue(kt + 1, st ^ 1);
        comp(st);
    }

#pragma unroll
    for (int mt = 0; mt < 4; ++mt) {
        size_t r0 = rowBase + wm * 64 + mt * 16 + (lane >> 2);
#pragma unroll
        for (int nt = 0; nt < 4; ++nt) {
            int cb = colBase + wn * 32 + nt * 8 + ((lane & 3) << 1);
            float2 bs = *(const float2*)(bias + cb);
            float2 o0 = make_float2(acc[mt][nt][0] + bs.x, acc[mt][nt][1] + bs.y);
            float2 o1 = make_float2(acc[mt][nt][2] + bs.x, acc[mt][nt][3] + bs.y);
            *(float2*)(Out + r0 * HID + cb)       = o0;
            *(float2*)(Out + (r0 + 8) * HID + cb) = o1;
        }
    }
}

// ============================================================================
// Scan summary pass: chunk-level (P, S) only; NO per-step stores.
//   a_t = sigmoid(-k_t), b_t = sigmoid(k_t)*g(p_t)
//   S_t = a_t S_{t-1} + b_t,  P_t = a_t P_{t-1}
// ============================================================================
__global__ void __launch_bounds__(128) scan_summary() {
    int b     = blockIdx.x >> 6;
    int chunk = (blockIdx.x >> 2) & 15;
    int c     = (blockIdx.x & 3) * 128 + threadIdx.x;
    size_t base = ((size_t)b * SEQ + chunk * TC) * HID + c;

    float S = 0.f, P = 1.f;
#pragma unroll 8
    for (int t = 0; t < TC; ++t) {
        size_t o = base + (size_t)t * HID;
        float kv = __ldcs(g_k + o);
        float pv = __ldcs(g_p + o);
        float ek = __expf(-kv);
        float z  = __fdividef(1.f, 1.f + ek);
        float a  = ek * z;
        float gp = (pv >= 0.f) ? (pv + 0.5f)
                               : __fdividef(1.f, 1.f + __expf(-pv));
        S = fmaf(a, S, z * gp);
        P *= a;
    }
    g_cA[(b * NC + chunk) * HID + c] = P;
    g_cB[(b * NC + chunk) * HID + c] = S;
}

// ============================================================================
// Chain chunk summaries; emit per-chunk h_in and final hiddens.
// ============================================================================
__global__ void __launch_bounds__(256) scanB(const float* __restrict__ h0l,
                                             float* __restrict__ hid_out) {
    int idx = blockIdx.x * 256 + threadIdx.x;   // 16384
    int b = idx >> 9, c = idx & 511;
    float x0 = h0l[b * HID + c];
    float h = (x0 >= 0.f) ? (x0 + 0.5f)
                          : __fdividef(1.f, 1.f + __expf(-x0));
#pragma unroll
    for (int j = 0; j < NC; ++j) {
        g_hin[(b * NC + j) * HID + c] = h;
        h = fmaf(g_cA[(b * NC + j) * HID + c], h, g_cB[(b * NC + j) * HID + c]);
    }
    hid_out[b * HID + c] = h;
}

// ============================================================================
// Fused scan + LayerNorm + residual (+ bf16 split for next layer's GEMM).
// One block per (b, chunk): 512 threads = channels; 128 sequential t-steps.
// Double-buffered block reduction: one __syncthreads per step.
// ============================================================================
__global__ void __launch_bounds__(512) scan_ln(const float* __restrict__ resid,
                                               const float* __restrict__ gamma,
                                               const float* __restrict__ beta,
                                               float* __restrict__ outp,
                                               int write_split) {
    __shared__ float red[2][2][16];
    int b = blockIdx.x >> 4, chunk = blockIdx.x & 15;
    int c = threadIdx.x, lane = c & 31, warp = c >> 5;

    float h  = g_hin[(b * NC + chunk) * HID + c];
    float gm = __ldg(gamma + c);
    float bt = __ldg(beta + c);
    size_t base = ((size_t)b * SEQ + chunk * TC) * HID + c;

    float kv = __ldcs(g_k + base);
    float pv = __ldcs(g_p + base);
    for (int t = 0; t < TC; ++t) {
        size_t o = base + (size_t)t * HID;
        float kn = 0.f, pn = 0.f;
        if (t + 1 < TC) {
            kn = __ldcs(g_k + o + HID);
            pn = __ldcs(g_p + o + HID);
        }
        float ek = __expf(-kv);
        float z  = __fdividef(1.f, 1.f + ek);
        float a  = ek * z;
        float gp = (pv >= 0.f) ? (pv + 0.5f)
                               : __fdividef(1.f, 1.f + __expf(-pv));
        h = fmaf(a, h, z * gp);

        float s = h, s2 = h * h;
#pragma unroll
        for (int off = 16; off; off >>= 1) {
            s  += __shfl_xor_sync(0xffffffffu, s,  off);
            s2 += __shfl_xor_sync(0xffffffffu, s2, off);
        }
        int tb = t & 1;
        if (lane == 0) { red[tb][0][warp] = s; red[tb][1][warp] = s2; }
        __syncthreads();
        s = 0.f; s2 = 0.f;
#pragma unroll
        for (int w = 0; w < 16; ++w) { s += red[tb][0][w]; s2 += red[tb][1][w]; }

        float mu   = s * (1.f / HID);
        float var  = fmaf(s2, 1.f / HID, -mu * mu);
        float rstd = rsqrtf(var + 1e-5f);
        float ov = (h - mu) * rstd * gm + bt + resid[o];
        outp[o] = ov;
        if (write_split) {
            __nv_bfloat16 hi = __float2bfloat16(ov);
            g_Ah[o] = hi;
            g_Al[o] = __float2bfloat16(ov - __bfloat162float(hi));
        }
        kv = kn; pv = pn;
    }
}

// ============================================================================
extern "C" void kernel_launch(void* const* d_in, const int* in_sizes, int n_in,
                              void* d_out, int out_size)
{
    const float* x     = (const float*)d_in[0];
    const float* h0    = (const float*)d_in[1];
    const float* Wz    = (const float*)d_in[2];
    const float* bz    = (const float*)d_in[3];
    const float* Wh    = (const float*)d_in[4];
    const float* bh    = (const float*)d_in[5];
    const float* gamma = (const float*)d_in[6];
    const float* beta  = (const float*)d_in[7];

    float* out_cur = (float*)d_out;                       // (B, T, H)
    float* out_hid = out_cur + (size_t)MTOT * HID;        // (L, B, H)

    cudaFuncSetAttribute(gates_gemm,
                         cudaFuncAttributeMaxDynamicSharedMemorySize, SMEM_BYTES);

    split_w<<<(NLAYERS * HID * HID) / 256, 256>>>(Wz, Wh);
    split_x<<<(MTOT * HID / 2) / 256, 256>>>(x);

    const float* cur = x;
    for (int i = 0; i < NLAYERS; ++i) {
        gates_gemm<<<dim3(8, MTOT / BM), 256, SMEM_BYTES>>>(
            i, bz + i * HID, bh + i * HID);
        scan_summary<<<BATCH * NC * 4, 128>>>();
        scanB<<<64, 256>>>(h0 + (size_t)i * BATCH * HID,
                           out_hid + (size_t)i * BATCH * HID);
        scan_ln<<<BATCH * NC, 512>>>(cur, gamma + i * HID, beta + i * HID,
                                     out_cur, (i < NLAYERS - 1) ? 1 : 0);
        cur = out_cur;
    }
}

// round 5
// speedup vs baseline: 1.0976x; 1.0976x over previous
#include <cuda_runtime.h>
#include <cuda_bf16.h>
#include <cstdint>

#define NLAYERS 4
#define HID 512
#define BATCH 32
#define SEQ 2048
#define MTOT (BATCH*SEQ)          // 65536
#define NC 32                     // scan chunks
#define TC (SEQ/NC)               // 64 steps per chunk
#define STEP 8                    // timesteps per reduction round in scan_ln

// ---------------- GEMM tiling ----------------
#define BM 128
#define BN 128
#define BK 32
#define LDA 40                    // BK + 8 pad (row = 80B)
#define LDB 136                   // BN + 8 pad (row = 272B)
#define STAGE_EL (2*BM*LDA + 2*BK*LDB)            // 18944 bf16
#define SMEM_BYTES (2*STAGE_EL*2)                 // 75776 bytes

// ---------------- scratch ----------------
__device__ float g_k[(size_t)MTOT * HID];
__device__ float g_p[(size_t)MTOT * HID];
__device__ __nv_bfloat16 g_Ah[(size_t)MTOT * HID];
__device__ __nv_bfloat16 g_Al[(size_t)MTOT * HID];
__device__ __nv_bfloat16 g_Wsp_hi[(size_t)NLAYERS * 2 * HID * HID];
__device__ __nv_bfloat16 g_Wsp_lo[(size_t)NLAYERS * 2 * HID * HID];
__device__ float g_cA[BATCH * NC * HID];
__device__ float g_cB[BATCH * NC * HID];
__device__ float g_hin[BATCH * NC * HID];

// ---------------- helpers ----------------
__device__ __forceinline__ uint32_t saddr(const void* p) {
    return (uint32_t)__cvta_generic_to_shared(p);
}
__device__ __forceinline__ void cpasync16(void* smem, const void* g) {
    asm volatile("cp.async.cg.shared.global [%0], [%1], 16;"
                 :: "r"(saddr(smem)), "l"(g));
}
__device__ __forceinline__ void cp_commit() {
    asm volatile("cp.async.commit_group;");
}
__device__ __forceinline__ void cp_wait0() {
    asm volatile("cp.async.wait_group 0;");
}
__device__ __forceinline__ void ldm_x4(uint32_t* r, uint32_t a) {
    asm volatile("ldmatrix.sync.aligned.m8n8.x4.shared.b16 {%0,%1,%2,%3}, [%4];"
                 : "=r"(r[0]), "=r"(r[1]), "=r"(r[2]), "=r"(r[3]) : "r"(a));
}
__device__ __forceinline__ void ldm_x2t(uint32_t* r, uint32_t a) {
    asm volatile("ldmatrix.sync.aligned.m8n8.x2.trans.shared.b16 {%0,%1}, [%2];"
                 : "=r"(r[0]), "=r"(r[1]) : "r"(a));
}
__device__ __forceinline__ void mma16816(float* c, const uint32_t* a, const uint32_t* b) {
    asm volatile(
        "mma.sync.aligned.m16n8k16.row.col.f32.bf16.bf16.f32 "
        "{%0,%1,%2,%3}, {%4,%5,%6,%7}, {%8,%9}, {%0,%1,%2,%3};"
        : "+f"(c[0]), "+f"(c[1]), "+f"(c[2]), "+f"(c[3])
        : "r"(a[0]), "r"(a[1]), "r"(a[2]), "r"(a[3]), "r"(b[0]), "r"(b[1]));
}
__device__ __forceinline__ void split2(float x, float y,
                                       __nv_bfloat16* hp, __nv_bfloat16* lp) {
    __nv_bfloat16 hx = __float2bfloat16(x);
    __nv_bfloat16 hy = __float2bfloat16(y);
    __nv_bfloat16 lx = __float2bfloat16(x - __bfloat162float(hx));
    __nv_bfloat16 ly = __float2bfloat16(y - __bfloat162float(hy));
    *reinterpret_cast<__nv_bfloat162*>(hp) = __halves2bfloat162(hx, hy);
    *reinterpret_cast<__nv_bfloat162*>(lp) = __halves2bfloat162(lx, ly);
}

// ============================================================================
// One-shot conversion kernels
// ============================================================================
__global__ void __launch_bounds__(256) split_w(const float* __restrict__ Wz,
                                               const float* __restrict__ Wh) {
    size_t i = (size_t)blockIdx.x * 256 + threadIdx.x;    // over 4*512*512
    size_t l = i >> 18, r = i & ((1u << 18) - 1);
    float z = Wz[i], h = Wh[i];
    {
        size_t o = ((l * 2 + 0) << 18) + r;
        __nv_bfloat16 hi = __float2bfloat16(z);
        g_Wsp_hi[o] = hi;
        g_Wsp_lo[o] = __float2bfloat16(z - __bfloat162float(hi));
    }
    {
        size_t o = ((l * 2 + 1) << 18) + r;
        __nv_bfloat16 hi = __float2bfloat16(h);
        g_Wsp_hi[o] = hi;
        g_Wsp_lo[o] = __float2bfloat16(h - __bfloat162float(hi));
    }
}

__global__ void __launch_bounds__(256) split_x(const float* __restrict__ x) {
    size_t i = (size_t)blockIdx.x * 256 + threadIdx.x;    // over MTOT*HID/2
    float2 v = ((const float2*)x)[i];
    split2(v.x, v.y, g_Ah + 2 * i, g_Al + 2 * i);
}

// ============================================================================
// Fused dual GEMM (bf16x3): reads pre-split bf16 A and W via cp.async.
// grid = (8, MTOT/128): blockIdx.x = {4 n-tiles} x {z / h}.
// ============================================================================
__global__ void __launch_bounds__(256, 2) gates_gemm(
    int layer, const float* __restrict__ bz, const float* __restrict__ bh)
{
    extern __shared__ __align__(16) char smem_raw[];
    __nv_bfloat16* s = (__nv_bfloat16*)smem_raw;

    const int tid  = threadIdx.x;
    const int lane = tid & 31;
    const int warp = tid >> 5;
    const int wm   = warp >> 2;
    const int wn   = warp & 3;
    const int zsel = blockIdx.x >> 2;
    const int colBase = (blockIdx.x & 3) * BN;
    const size_t rowBase = (size_t)blockIdx.y * BM;

    const __nv_bfloat16* Wh_ = g_Wsp_hi + (((size_t)layer * 2 + zsel) << 18);
    const __nv_bfloat16* Wl_ = g_Wsp_lo + (((size_t)layer * 2 + zsel) << 18);
    const float* bias = zsel ? bh : bz;
    float*       Out  = zsel ? g_p : g_k;

    auto issue = [&](int kt, int st) {
        __nv_bfloat16* sb = s + st * STAGE_EL;
#pragma unroll
        for (int j = 0; j < 4; ++j) {                  // A: 1024 16B chunks
            int i = tid + 256 * j;
            int row = i >> 3, rem = i & 7, hl = rem >> 2, ch = rem & 3;
            const __nv_bfloat16* gsrc = (hl ? g_Al : g_Ah)
                + (rowBase + row) * HID + kt * BK + ch * 8;
            cpasync16(sb + hl * (BM * LDA) + row * LDA + ch * 8, gsrc);
        }
#pragma unroll
        for (int j = 0; j < 4; ++j) {                  // B: 1024 16B chunks
            int i = tid + 256 * j;
            int row = i >> 5, rem = i & 31, hl = rem >> 4, ch = rem & 15;
            const __nv_bfloat16* gsrc = (hl ? Wl_ : Wh_)
                + (size_t)(kt * BK + row) * HID + colBase + ch * 8;
            cpasync16(sb + 2 * BM * LDA + hl * (BK * LDB) + row * LDB + ch * 8, gsrc);
        }
        cp_commit();
    };

    float acc[4][4][4];
#pragma unroll
    for (int mt = 0; mt < 4; ++mt)
#pragma unroll
        for (int nt = 0; nt < 4; ++nt)
#pragma unroll
            for (int r = 0; r < 4; ++r) acc[mt][nt][r] = 0.f;

    auto comp = [&](int st) {
        const __nv_bfloat16* sAh = s + st * STAGE_EL;
        const __nv_bfloat16* sAl = sAh + BM * LDA;
        const __nv_bfloat16* sBh = sAh + 2 * BM * LDA;
        const __nv_bfloat16* sBl = sBh + BK * LDB;
#pragma unroll
        for (int ks = 0; ks < 2; ++ks) {
            uint32_t Bh[4][2], Bl[4][2];
#pragma unroll
            for (int nt = 0; nt < 4; ++nt) {
                int br = ks * 16 + (lane & 15);
                int bc = wn * 32 + nt * 8;
                ldm_x2t(Bh[nt], saddr(sBh + br * LDB + bc));
                ldm_x2t(Bl[nt], saddr(sBl + br * LDB + bc));
            }
#pragma unroll
            for (int mt = 0; mt < 4; ++mt) {
                uint32_t Ah[4], Al[4];
                int ar = wm * 64 + mt * 16 + (lane & 15);
                int ac = ks * 16 + ((lane >> 4) << 3);
                ldm_x4(Ah, saddr(sAh + ar * LDA + ac));
                ldm_x4(Al, saddr(sAl + ar * LDA + ac));
#pragma unroll
                for (int nt = 0; nt < 4; ++nt) {
                    mma16816(acc[mt][nt], Ah, Bh[nt]);
                    mma16816(acc[mt][nt], Ah, Bl[nt]);
                    mma16816(acc[mt][nt], Al, Bh[nt]);
                }
            }
        }
    };

    issue(0, 0);
    const int KI = HID / BK;    // 16
    for (int kt = 0; kt < KI; ++kt) {
        int st = kt & 1;
        cp_wait0();
        __syncthreads();
        if (kt + 1 < KI) issue(kt + 1, st ^ 1);
        comp(st);
    }

#pragma unroll
    for (int mt = 0; mt < 4; ++mt) {
        size_t r0 = rowBase + wm * 64 + mt * 16 + (lane >> 2);
#pragma unroll
        for (int nt = 0; nt < 4; ++nt) {
            int cb = colBase + wn * 32 + nt * 8 + ((lane & 3) << 1);
            float2 bs = *(const float2*)(bias + cb);
            float2 o0 = make_float2(acc[mt][nt][0] + bs.x, acc[mt][nt][1] + bs.y);
            float2 o1 = make_float2(acc[mt][nt][2] + bs.x, acc[mt][nt][3] + bs.y);
            *(float2*)(Out + r0 * HID + cb)       = o0;
            *(float2*)(Out + (r0 + 8) * HID + cb) = o1;
        }
    }
}

// ============================================================================
// Scan summary pass: chunk-level (P, S) only; NO per-step stores.
// grid = BATCH*NC*4 = 4096 blocks x 128 threads, TC=64 steps each.
// ============================================================================
__global__ void __launch_bounds__(128) scan_summary() {
    int b     = blockIdx.x >> 7;
    int chunk = (blockIdx.x >> 2) & (NC - 1);
    int c     = (blockIdx.x & 3) * 128 + threadIdx.x;
    size_t base = ((size_t)b * SEQ + chunk * TC) * HID + c;

    float S = 0.f, P = 1.f;
#pragma unroll 8
    for (int t = 0; t < TC; ++t) {
        size_t o = base + (size_t)t * HID;
        float kv = __ldcs(g_k + o);
        float pv = __ldcs(g_p + o);
        float ek = __expf(-kv);
        float z  = __fdividef(1.f, 1.f + ek);
        float a  = ek * z;
        float gp = (pv >= 0.f) ? (pv + 0.5f)
                               : __fdividef(1.f, 1.f + __expf(-pv));
        S = fmaf(a, S, z * gp);
        P *= a;
    }
    g_cA[(b * NC + chunk) * HID + c] = P;
    g_cB[(b * NC + chunk) * HID + c] = S;
}

// ============================================================================
// Chain chunk summaries; emit per-chunk h_in and final hiddens.
// ============================================================================
__global__ void __launch_bounds__(256) scanB(const float* __restrict__ h0l,
                                             float* __restrict__ hid_out) {
    int idx = blockIdx.x * 256 + threadIdx.x;   // 16384
    int b = idx >> 9, c = idx & 511;
    float x0 = h0l[b * HID + c];
    float h = (x0 >= 0.f) ? (x0 + 0.5f)
                          : __fdividef(1.f, 1.f + __expf(-x0));
#pragma unroll
    for (int j = 0; j < NC; ++j) {
        g_hin[(b * NC + j) * HID + c] = h;
        h = fmaf(g_cA[(b * NC + j) * HID + c], h, g_cB[(b * NC + j) * HID + c]);
    }
    hid_out[b * HID + c] = h;
}

// ============================================================================
// Fused scan + LayerNorm + residual (+ bf16 split for next layer's GEMM).
// One block per (b, chunk): 512 threads = channels; TC=64 steps processed in
// STEP=8 batches -> 2 barriers + one two-level reduction per 8 steps.
// ============================================================================
__global__ void __launch_bounds__(512) scan_ln(const float* __restrict__ resid,
                                               const float* __restrict__ gamma,
                                               const float* __restrict__ beta,
                                               float* __restrict__ outp,
                                               int write_split) {
    __shared__ float red[16][16];     // [warp][8 x s, 8 x s2]
    __shared__ float bcast[2][STEP];  // [mu | rstd][step]
    int b = blockIdx.x >> 5, chunk = blockIdx.x & (NC - 1);
    int c = threadIdx.x, lane = c & 31, warp = c >> 5;

    float h  = g_hin[(b * NC + chunk) * HID + c];
    float gm = __ldg(gamma + c);
    float bt = __ldg(beta + c);
    size_t base = ((size_t)b * SEQ + chunk * TC) * HID + c;

    for (int t0 = 0; t0 < TC; t0 += STEP) {
        float k8[STEP], p8[STEP], r8[STEP], h8[STEP], s8[STEP], q8[STEP];
#pragma unroll
        for (int j = 0; j < STEP; ++j) {          // batched loads (MLP ~24)
            size_t o = base + (size_t)(t0 + j) * HID;
            k8[j] = __ldcs(g_k + o);
            p8[j] = __ldcs(g_p + o);
            r8[j] = __ldg(resid + o);
        }
#pragma unroll
        for (int j = 0; j < STEP; ++j) {          // 8-step h chain
            float ek = __expf(-k8[j]);
            float z  = __fdividef(1.f, 1.f + ek);
            float a  = ek * z;
            float gp = (p8[j] >= 0.f) ? (p8[j] + 0.5f)
                                      : __fdividef(1.f, 1.f + __expf(-p8[j]));
            h = fmaf(a, h, z * gp);
            h8[j] = h;
            s8[j] = h;
            q8[j] = h * h;
        }
        // warp butterfly: 16 independent reductions, full ILP
#pragma unroll
        for (int off = 16; off; off >>= 1) {
#pragma unroll
            for (int j = 0; j < STEP; ++j) {
                s8[j] += __shfl_xor_sync(0xffffffffu, s8[j], off);
                q8[j] += __shfl_xor_sync(0xffffffffu, q8[j], off);
            }
        }
        if (lane == 0) {
#pragma unroll
            for (int j = 0; j < STEP; ++j) {
                red[warp][j]        = s8[j];
                red[warp][j + STEP] = q8[j];
            }
        }
        __syncthreads();
        if (warp == 0) {
            float v = 0.f;
            if (lane < 16) {
#pragma unroll
                for (int w = 0; w < 16; ++w) v += red[w][lane];
            }
            float vq = __shfl_down_sync(0xffffffffu, v, STEP);
            if (lane < STEP) {
                float mu  = v * (1.f / HID);
                float var = fmaf(vq, 1.f / HID, -mu * mu);
                bcast[0][lane] = mu;
                bcast[1][lane] = rsqrtf(var + 1e-5f);
            }
        }
        __syncthreads();
#pragma unroll
        for (int j = 0; j < STEP; ++j) {
            size_t o = base + (size_t)(t0 + j) * HID;
            float mu = bcast[0][j], rstd = bcast[1][j];
            float ov = (h8[j] - mu) * rstd * gm + bt + r8[j];
            outp[o] = ov;
            if (write_split) {
                __nv_bfloat16 hi = __float2bfloat16(ov);
                g_Ah[o] = hi;
                g_Al[o] = __float2bfloat16(ov - __bfloat162float(hi));
            }
        }
    }
}

// ============================================================================
extern "C" void kernel_launch(void* const* d_in, const int* in_sizes, int n_in,
                              void* d_out, int out_size)
{
    const float* x     = (const float*)d_in[0];
    const float* h0    = (const float*)d_in[1];
    const float* Wz    = (const float*)d_in[2];
    const float* bz    = (const float*)d_in[3];
    const float* Wh    = (const float*)d_in[4];
    const float* bh    = (const float*)d_in[5];
    const float* gamma = (const float*)d_in[6];
    const float* beta  = (const float*)d_in[7];

    float* out_cur = (float*)d_out;                       // (B, T, H)
    float* out_hid = out_cur + (size_t)MTOT * HID;        // (L, B, H)

    cudaFuncSetAttribute(gates_gemm,
                         cudaFuncAttributeMaxDynamicSharedMemorySize, SMEM_BYTES);

    split_w<<<(NLAYERS * HID * HID) / 256, 256>>>(Wz, Wh);
    split_x<<<(MTOT * HID / 2) / 256, 256>>>(x);

    const float* cur = x;
    for (int i = 0; i < NLAYERS; ++i) {
        gates_gemm<<<dim3(8, MTOT / BM), 256, SMEM_BYTES>>>(
            i, bz + i * HID, bh + i * HID);
        scan_summary<<<BATCH * NC * 4, 128>>>();
        scanB<<<64, 256>>>(h0 + (size_t)i * BATCH * HID,
                           out_hid + (size_t)i * BATCH * HID);
        scan_ln<<<BATCH * NC, 512>>>(cur, gamma + i * HID, beta + i * HID,
                                     out_cur, (i < NLAYERS - 1) ? 1 : 0);
        cur = out_cur;
    }
}

// round 6
// speedup vs baseline: 1.1068x; 1.0084x over previous
#include <cuda_runtime.h>
#include <cuda_bf16.h>
#include <cstdint>

#define NLAYERS 4
#define HID 512
#define BATCH 32
#define SEQ 2048
#define MTOT (BATCH*SEQ)          // 65536
#define NC 64                     // scan chunks
#define TC (SEQ/NC)               // 32 steps per chunk
#define STEP 8                    // timesteps per reduction round in scan_ln

// ---------------- GEMM tiling ----------------
#define BM 128
#define BN 128
#define BK 32
#define LDA 40                    // BK + 8 pad (row = 80B)
#define LDB 136                   // BN + 8 pad (row = 272B)
#define STAGE_EL (2*BM*LDA + 2*BK*LDB)            // 18944 bf16
#define SMEM_BYTES (2*STAGE_EL*2)                 // 75776 bytes

// ---------------- scratch ----------------
__device__ float g_k[(size_t)MTOT * HID];
__device__ float g_p[(size_t)MTOT * HID];
__device__ __nv_bfloat16 g_Ah[(size_t)MTOT * HID];
__device__ __nv_bfloat16 g_Al[(size_t)MTOT * HID];
__device__ __nv_bfloat16 g_Wsp_hi[(size_t)NLAYERS * 2 * HID * HID];
__device__ __nv_bfloat16 g_Wsp_lo[(size_t)NLAYERS * 2 * HID * HID];
__device__ float g_cA[BATCH * NC * HID];
__device__ float g_cB[BATCH * NC * HID];
__device__ float g_hin[BATCH * NC * HID];

// ---------------- helpers ----------------
__device__ __forceinline__ uint32_t saddr(const void* p) {
    return (uint32_t)__cvta_generic_to_shared(p);
}
__device__ __forceinline__ void cpasync16(void* smem, const void* g) {
    asm volatile("cp.async.cg.shared.global [%0], [%1], 16;"
                 :: "r"(saddr(smem)), "l"(g));
}
__device__ __forceinline__ void cp_commit() {
    asm volatile("cp.async.commit_group;");
}
__device__ __forceinline__ void cp_wait0() {
    asm volatile("cp.async.wait_group 0;");
}
__device__ __forceinline__ void ldm_x4(uint32_t* r, uint32_t a) {
    asm volatile("ldmatrix.sync.aligned.m8n8.x4.shared.b16 {%0,%1,%2,%3}, [%4];"
                 : "=r"(r[0]), "=r"(r[1]), "=r"(r[2]), "=r"(r[3]) : "r"(a));
}
__device__ __forceinline__ void ldm_x2t(uint32_t* r, uint32_t a) {
    asm volatile("ldmatrix.sync.aligned.m8n8.x2.trans.shared.b16 {%0,%1}, [%2];"
                 : "=r"(r[0]), "=r"(r[1]) : "r"(a));
}
__device__ __forceinline__ void mma16816(float* c, const uint32_t* a, const uint32_t* b) {
    asm volatile(
        "mma.sync.aligned.m16n8k16.row.col.f32.bf16.bf16.f32 "
        "{%0,%1,%2,%3}, {%4,%5,%6,%7}, {%8,%9}, {%0,%1,%2,%3};"
        : "+f"(c[0]), "+f"(c[1]), "+f"(c[2]), "+f"(c[3])
        : "r"(a[0]), "r"(a[1]), "r"(a[2]), "r"(a[3]), "r"(b[0]), "r"(b[1]));
}
__device__ __forceinline__ void split2(float x, float y,
                                       __nv_bfloat16* hp, __nv_bfloat16* lp) {
    __nv_bfloat16 hx = __float2bfloat16(x);
    __nv_bfloat16 hy = __float2bfloat16(y);
    __nv_bfloat16 lx = __float2bfloat16(x - __bfloat162float(hx));
    __nv_bfloat16 ly = __float2bfloat16(y - __bfloat162float(hy));
    *reinterpret_cast<__nv_bfloat162*>(hp) = __halves2bfloat162(hx, hy);
    *reinterpret_cast<__nv_bfloat162*>(lp) = __halves2bfloat162(lx, ly);
}

// ============================================================================
// One-shot conversion kernels
// ============================================================================
__global__ void __launch_bounds__(256) split_w(const float* __restrict__ Wz,
                                               const float* __restrict__ Wh) {
    size_t i = (size_t)blockIdx.x * 256 + threadIdx.x;    // over 4*512*512
    size_t l = i >> 18, r = i & ((1u << 18) - 1);
    float z = Wz[i], h = Wh[i];
    {
        size_t o = ((l * 2 + 0) << 18) + r;
        __nv_bfloat16 hi = __float2bfloat16(z);
        g_Wsp_hi[o] = hi;
        g_Wsp_lo[o] = __float2bfloat16(z - __bfloat162float(hi));
    }
    {
        size_t o = ((l * 2 + 1) << 18) + r;
        __nv_bfloat16 hi = __float2bfloat16(h);
        g_Wsp_hi[o] = hi;
        g_Wsp_lo[o] = __float2bfloat16(h - __bfloat162float(hi));
    }
}

__global__ void __launch_bounds__(256) split_x(const float* __restrict__ x) {
    size_t i = (size_t)blockIdx.x * 256 + threadIdx.x;    // over MTOT*HID/2
    float2 v = ((const float2*)x)[i];
    split2(v.x, v.y, g_Ah + 2 * i, g_Al + 2 * i);
}

// ============================================================================
// Fused dual GEMM (bf16x3): reads pre-split bf16 A and W via cp.async.
// grid = (8, MTOT/128): blockIdx.x = {4 n-tiles} x {z / h}.
// ============================================================================
__global__ void __launch_bounds__(256, 2) gates_gemm(
    int layer, const float* __restrict__ bz, const float* __restrict__ bh)
{
    extern __shared__ __align__(16) char smem_raw[];
    __nv_bfloat16* s = (__nv_bfloat16*)smem_raw;

    const int tid  = threadIdx.x;
    const int lane = tid & 31;
    const int warp = tid >> 5;
    const int wm   = warp >> 2;
    const int wn   = warp & 3;
    const int zsel = blockIdx.x >> 2;
    const int colBase = (blockIdx.x & 3) * BN;
    const size_t rowBase = (size_t)blockIdx.y * BM;

    const __nv_bfloat16* Wh_ = g_Wsp_hi + (((size_t)layer * 2 + zsel) << 18);
    const __nv_bfloat16* Wl_ = g_Wsp_lo + (((size_t)layer * 2 + zsel) << 18);
    const float* bias = zsel ? bh : bz;
    float*       Out  = zsel ? g_p : g_k;

    auto issue = [&](int kt, int st) {
        __nv_bfloat16* sb = s + st * STAGE_EL;
#pragma unroll
        for (int j = 0; j < 4; ++j) {                  // A: 1024 16B chunks
            int i = tid + 256 * j;
            int row = i >> 3, rem = i & 7, hl = rem >> 2, ch = rem & 3;
            const __nv_bfloat16* gsrc = (hl ? g_Al : g_Ah)
                + (rowBase + row) * HID + kt * BK + ch * 8;
            cpasync16(sb + hl * (BM * LDA) + row * LDA + ch * 8, gsrc);
        }
#pragma unroll
        for (int j = 0; j < 4; ++j) {                  // B: 1024 16B chunks
            int i = tid + 256 * j;
            int row = i >> 5, rem = i & 31, hl = rem >> 4, ch = rem & 15;
            const __nv_bfloat16* gsrc = (hl ? Wl_ : Wh_)
                + (size_t)(kt * BK + row) * HID + colBase + ch * 8;
            cpasync16(sb + 2 * BM * LDA + hl * (BK * LDB) + row * LDB + ch * 8, gsrc);
        }
        cp_commit();
    };

    float acc[4][4][4];
#pragma unroll
    for (int mt = 0; mt < 4; ++mt)
#pragma unroll
        for (int nt = 0; nt < 4; ++nt)
#pragma unroll
            for (int r = 0; r < 4; ++r) acc[mt][nt][r] = 0.f;

    auto comp = [&](int st) {
        const __nv_bfloat16* sAh = s + st * STAGE_EL;
        const __nv_bfloat16* sAl = sAh + BM * LDA;
        const __nv_bfloat16* sBh = sAh + 2 * BM * LDA;
        const __nv_bfloat16* sBl = sBh + BK * LDB;
#pragma unroll
        for (int ks = 0; ks < 2; ++ks) {
            uint32_t Bh[4][2], Bl[4][2];
#pragma unroll
            for (int nt = 0; nt < 4; ++nt) {
                int br = ks * 16 + (lane & 15);
                int bc = wn * 32 + nt * 8;
                ldm_x2t(Bh[nt], saddr(sBh + br * LDB + bc));
                ldm_x2t(Bl[nt], saddr(sBl + br * LDB + bc));
            }
#pragma unroll
            for (int mt = 0; mt < 4; ++mt) {
                uint32_t Ah[4], Al[4];
                int ar = wm * 64 + mt * 16 + (lane & 15);
                int ac = ks * 16 + ((lane >> 4) << 3);
                ldm_x4(Ah, saddr(sAh + ar * LDA + ac));
                ldm_x4(Al, saddr(sAl + ar * LDA + ac));
#pragma unroll
                for (int nt = 0; nt < 4; ++nt) {
                    mma16816(acc[mt][nt], Ah, Bh[nt]);
                    mma16816(acc[mt][nt], Ah, Bl[nt]);
                    mma16816(acc[mt][nt], Al, Bh[nt]);
                }
            }
        }
    };

    issue(0, 0);
    const int KI = HID / BK;    // 16
    for (int kt = 0; kt < KI; ++kt) {
        int st = kt & 1;
        cp_wait0();
        __syncthreads();
        if (kt + 1 < KI) issue(kt + 1, st ^ 1);
        comp(st);
    }

#pragma unroll
    for (int mt = 0; mt < 4; ++mt) {
        size_t r0 = rowBase + wm * 64 + mt * 16 + (lane >> 2);
#pragma unroll
        for (int nt = 0; nt < 4; ++nt) {
            int cb = colBase + wn * 32 + nt * 8 + ((lane & 3) << 1);
            float2 bs = *(const float2*)(bias + cb);
            float2 o0 = make_float2(acc[mt][nt][0] + bs.x, acc[mt][nt][1] + bs.y);
            float2 o1 = make_float2(acc[mt][nt][2] + bs.x, acc[mt][nt][3] + bs.y);
            *(float2*)(Out + r0 * HID + cb)       = o0;
            *(float2*)(Out + (r0 + 8) * HID + cb) = o1;
        }
    }
}

// ============================================================================
// Scan summary pass: chunk-level (P, S) only; NO per-step stores.
// grid = BATCH*NC*4 = 8192 blocks x 128 threads, TC=32 steps each.
// ============================================================================
__global__ void __launch_bounds__(128) scan_summary() {
    int b     = blockIdx.x >> 8;                  // NC*4 = 256 blocks per batch
    int chunk = (blockIdx.x >> 2) & (NC - 1);
    int c     = (blockIdx.x & 3) * 128 + threadIdx.x;
    size_t base = ((size_t)b * SEQ + chunk * TC) * HID + c;

    float S = 0.f, P = 1.f;
#pragma unroll 8
    for (int t = 0; t < TC; ++t) {
        size_t o = base + (size_t)t * HID;
        float kv = __ldcs(g_k + o);
        float pv = __ldcs(g_p + o);
        float ek = __expf(-kv);
        float z  = __fdividef(1.f, 1.f + ek);
        float a  = ek * z;
        float gp = (pv >= 0.f) ? (pv + 0.5f)
                               : __fdividef(1.f, 1.f + __expf(-pv));
        S = fmaf(a, S, z * gp);
        P *= a;
    }
    g_cA[(b * NC + chunk) * HID + c] = P;
    g_cB[(b * NC + chunk) * HID + c] = S;
}

// ============================================================================
// Chain chunk summaries; emit per-chunk h_in and final hiddens.
// ============================================================================
__global__ void __launch_bounds__(256) scanB(const float* __restrict__ h0l,
                                             float* __restrict__ hid_out) {
    int idx = blockIdx.x * 256 + threadIdx.x;   // 16384
    int b = idx >> 9, c = idx & 511;
    float x0 = h0l[b * HID + c];
    float h = (x0 >= 0.f) ? (x0 + 0.5f)
                          : __fdividef(1.f, 1.f + __expf(-x0));
#pragma unroll
    for (int j = 0; j < NC; ++j) {
        g_hin[(b * NC + j) * HID + c] = h;
        h = fmaf(g_cA[(b * NC + j) * HID + c], h, g_cB[(b * NC + j) * HID + c]);
    }
    hid_out[b * HID + c] = h;
}

// ============================================================================
// Fused scan + LayerNorm + residual (+ bf16 split for next layer's GEMM).
// One block per (b, chunk): 256 threads x 2 channels (float2); TC=32 steps in
// STEP=8 batches. 2 blocks/SM co-residency hides the per-round barriers.
// ============================================================================
__global__ void __launch_bounds__(256, 2) scan_ln(const float* __restrict__ resid,
                                                  const float* __restrict__ gamma,
                                                  const float* __restrict__ beta,
                                                  float* __restrict__ outp,
                                                  int write_split) {
    __shared__ float red[8][16];      // [warp][8 x s, 8 x s2]
    __shared__ float bcast[2][STEP];  // [mu | rstd][step]
    int b = blockIdx.x >> 6, chunk = blockIdx.x & (NC - 1);
    int c2 = threadIdx.x, lane = c2 & 31, warp = c2 >> 5;
    const int H2 = HID / 2;   // 256 float2 per row

    float2 h   = ((const float2*)g_hin)[(b * NC + chunk) * H2 + c2];
    float2 gm  = __ldg((const float2*)gamma + c2);
    float2 bt  = __ldg((const float2*)beta + c2);
    size_t base2 = ((size_t)b * SEQ + chunk * TC) * H2 + c2;   // float2 index

    const float2* k2g = (const float2*)g_k;
    const float2* p2g = (const float2*)g_p;
    const float2* r2g = (const float2*)resid;
    float2*       o2g = (float2*)outp;

    for (int t0 = 0; t0 < TC; t0 += STEP) {
        float2 k8[STEP], p8[STEP], r8[STEP], h8[STEP];
        float s8[STEP], q8[STEP];
#pragma unroll
        for (int j = 0; j < STEP; ++j) {          // batched loads (MLP ~24)
            size_t o = base2 + (size_t)(t0 + j) * H2;
            k8[j] = __ldcs(k2g + o);
            p8[j] = __ldcs(p2g + o);
            r8[j] = __ldg(r2g + o);
        }
#pragma unroll
        for (int j = 0; j < STEP; ++j) {          // 8-step h chain (2 ch)
            float ekx = __expf(-k8[j].x), eky = __expf(-k8[j].y);
            float zx  = __fdividef(1.f, 1.f + ekx);
            float zy  = __fdividef(1.f, 1.f + eky);
            float ax  = ekx * zx, ay = eky * zy;
            float gpx = (p8[j].x >= 0.f) ? (p8[j].x + 0.5f)
                                         : __fdividef(1.f, 1.f + __expf(-p8[j].x));
            float gpy = (p8[j].y >= 0.f) ? (p8[j].y + 0.5f)
                                         : __fdividef(1.f, 1.f + __expf(-p8[j].y));
            h.x = fmaf(ax, h.x, zx * gpx);
            h.y = fmaf(ay, h.y, zy * gpy);
            h8[j] = h;
            s8[j] = h.x + h.y;
            q8[j] = h.x * h.x + h.y * h.y;
        }
        // warp butterfly: 16 independent reductions, full ILP
#pragma unroll
        for (int off = 16; off; off >>= 1) {
#pragma unroll
            for (int j = 0; j < STEP; ++j) {
                s8[j] += __shfl_xor_sync(0xffffffffu, s8[j], off);
                q8[j] += __shfl_xor_sync(0xffffffffu, q8[j], off);
            }
        }
        if (lane == 0) {
#pragma unroll
            for (int j = 0; j < STEP; ++j) {
                red[warp][j]        = s8[j];
                red[warp][j + STEP] = q8[j];
            }
        }
        __syncthreads();
        if (warp == 0) {
            float v = 0.f;
            if (lane < 16) {
#pragma unroll
                for (int w = 0; w < 8; ++w) v += red[w][lane];
            }
            float vq = __shfl_down_sync(0xffffffffu, v, STEP);
            if (lane < STEP) {
                float mu  = v * (1.f / HID);
                float var = fmaf(vq, 1.f / HID, -mu * mu);
                bcast[0][lane] = mu;
                bcast[1][lane] = rsqrtf(var + 1e-5f);
            }
        }
        __syncthreads();
#pragma unroll
        for (int j = 0; j < STEP; ++j) {
            size_t o = base2 + (size_t)(t0 + j) * H2;
            float mu = bcast[0][j], rstd = bcast[1][j];
            float2 ov;
            ov.x = (h8[j].x - mu) * rstd * gm.x + bt.x + r8[j].x;
            ov.y = (h8[j].y - mu) * rstd * gm.y + bt.y + r8[j].y;
            o2g[o] = ov;
            if (write_split)
                split2(ov.x, ov.y, g_Ah + 2 * o, g_Al + 2 * o);
        }
    }
}

// ============================================================================
extern "C" void kernel_launch(void* const* d_in, const int* in_sizes, int n_in,
                              void* d_out, int out_size)
{
    const float* x     = (const float*)d_in[0];
    const float* h0    = (const float*)d_in[1];
    const float* Wz    = (const float*)d_in[2];
    const float* bz    = (const float*)d_in[3];
    const float* Wh    = (const float*)d_in[4];
    const float* bh    = (const float*)d_in[5];
    const float* gamma = (const float*)d_in[6];
    const float* beta  = (const float*)d_in[7];

    float* out_cur = (float*)d_out;                       // (B, T, H)
    float* out_hid = out_cur + (size_t)MTOT * HID;        // (L, B, H)

    cudaFuncSetAttribute(gates_gemm,
                         cudaFuncAttributeMaxDynamicSharedMemorySize, SMEM_BYTES);

    split_w<<<(NLAYERS * HID * HID) / 256, 256>>>(Wz, Wh);
    split_x<<<(MTOT * HID / 2) / 256, 256>>>(x);

    const float* cur = x;
    for (int i = 0; i < NLAYERS; ++i) {
        gates_gemm<<<dim3(8, MTOT / BM), 256, SMEM_BYTES>>>(
            i, bz + i * HID, bh + i * HID);
        scan_summary<<<BATCH * NC * 4, 128>>>();
        scanB<<<64, 256>>>(h0 + (size_t)i * BATCH * HID,
                           out_hid + (size_t)i * BATCH * HID);
        scan_ln<<<BATCH * NC, 256>>>(cur, gamma + i * HID, beta + i * HID,
                                     out_cur, (i < NLAYERS - 1) ? 1 : 0);
        cur = out_cur;
    }
}

// round 7
// speedup vs baseline: 1.1514x; 1.0403x over previous
#include <cuda_runtime.h>
#include <cuda_bf16.h>
#include <cuda_fp16.h>
#include <cstdint>

#define NLAYERS 4
#define HID 512
#define BATCH 32
#define SEQ 2048
#define MTOT (BATCH*SEQ)          // 65536
#define NC 64                     // scan chunks
#define TC (SEQ/NC)               // 32 steps per chunk
#define STEP 8                    // timesteps per reduction round in scan_ln
#define H2 (HID/2)                // 256 channel-pairs per row

// ---------------- GEMM tiling ----------------
#define BM 128
#define BN 128
#define BK 32
#define LDA 40                    // BK + 8 pad (row = 80B)
#define LDB 136                   // BN + 8 pad (row = 272B)
#define STAGE_EL (2*BM*LDA + 2*BK*LDB)            // 18944 bf16
#define SMEM_BYTES (2*STAGE_EL*2)                 // 75776 bytes

// ---------------- scratch ----------------
__device__ __half g_kh[(size_t)MTOT * HID];       // z-gate pre-activation (fp16)
__device__ __half g_ph[(size_t)MTOT * HID];       // h~ pre-activation (fp16)
__device__ __nv_bfloat16 g_Ah[(size_t)MTOT * HID];
__device__ __nv_bfloat16 g_Al[(size_t)MTOT * HID];
__device__ __nv_bfloat16 g_Wsp_hi[(size_t)NLAYERS * 2 * HID * HID];
__device__ __nv_bfloat16 g_Wsp_lo[(size_t)NLAYERS * 2 * HID * HID];
__device__ float g_cA[BATCH * NC * HID];
__device__ float g_cB[BATCH * NC * HID];
__device__ float g_hin[BATCH * NC * HID];

// ---------------- helpers ----------------
__device__ __forceinline__ uint32_t saddr(const void* p) {
    return (uint32_t)__cvta_generic_to_shared(p);
}
__device__ __forceinline__ void cpasync16(void* smem, const void* g) {
    asm volatile("cp.async.cg.shared.global [%0], [%1], 16;"
                 :: "r"(saddr(smem)), "l"(g));
}
__device__ __forceinline__ void cp_commit() {
    asm volatile("cp.async.commit_group;");
}
__device__ __forceinline__ void cp_wait0() {
    asm volatile("cp.async.wait_group 0;");
}
__device__ __forceinline__ void ldm_x4(uint32_t* r, uint32_t a) {
    asm volatile("ldmatrix.sync.aligned.m8n8.x4.shared.b16 {%0,%1,%2,%3}, [%4];"
                 : "=r"(r[0]), "=r"(r[1]), "=r"(r[2]), "=r"(r[3]) : "r"(a));
}
__device__ __forceinline__ void ldm_x2t(uint32_t* r, uint32_t a) {
    asm volatile("ldmatrix.sync.aligned.m8n8.x2.trans.shared.b16 {%0,%1}, [%2];"
                 : "=r"(r[0]), "=r"(r[1]) : "r"(a));
}
__device__ __forceinline__ void mma16816(float* c, const uint32_t* a, const uint32_t* b) {
    asm volatile(
        "mma.sync.aligned.m16n8k16.row.col.f32.bf16.bf16.f32 "
        "{%0,%1,%2,%3}, {%4,%5,%6,%7}, {%8,%9}, {%0,%1,%2,%3};"
        : "+f"(c[0]), "+f"(c[1]), "+f"(c[2]), "+f"(c[3])
        : "r"(a[0]), "r"(a[1]), "r"(a[2]), "r"(a[3]), "r"(b[0]), "r"(b[1]));
}
__device__ __forceinline__ void split2(float x, float y,
                                       __nv_bfloat16* hp, __nv_bfloat16* lp) {
    __nv_bfloat16 hx = __float2bfloat16(x);
    __nv_bfloat16 hy = __float2bfloat16(y);
    __nv_bfloat16 lx = __float2bfloat16(x - __bfloat162float(hx));
    __nv_bfloat16 ly = __float2bfloat16(y - __bfloat162float(hy));
    *reinterpret_cast<__nv_bfloat162*>(hp) = __halves2bfloat162(hx, hy);
    *reinterpret_cast<__nv_bfloat162*>(lp) = __halves2bfloat162(lx, ly);
}

// ============================================================================
// One-shot conversion kernels
// ============================================================================
__global__ void __launch_bounds__(256) split_w(const float* __restrict__ Wz,
                                               const float* __restrict__ Wh) {
    size_t i = (size_t)blockIdx.x * 256 + threadIdx.x;    // over 4*512*512
    size_t l = i >> 18, r = i & ((1u << 18) - 1);
    float z = Wz[i], h = Wh[i];
    {
        size_t o = ((l * 2 + 0) << 18) + r;
        __nv_bfloat16 hi = __float2bfloat16(z);
        g_Wsp_hi[o] = hi;
        g_Wsp_lo[o] = __float2bfloat16(z - __bfloat162float(hi));
    }
    {
        size_t o = ((l * 2 + 1) << 18) + r;
        __nv_bfloat16 hi = __float2bfloat16(h);
        g_Wsp_hi[o] = hi;
        g_Wsp_lo[o] = __float2bfloat16(h - __bfloat162float(hi));
    }
}

__global__ void __launch_bounds__(256) split_x(const float* __restrict__ x) {
    size_t i = (size_t)blockIdx.x * 256 + threadIdx.x;    // over MTOT*HID/2
    float2 v = ((const float2*)x)[i];
    split2(v.x, v.y, g_Ah + 2 * i, g_Al + 2 * i);
}

// ============================================================================
// Fused dual GEMM (bf16x3): reads pre-split bf16 A and W via cp.async.
// grid = (8, MTOT/128): blockIdx.x = {4 n-tiles} x {z / h}.  fp16 output.
// ============================================================================
__global__ void __launch_bounds__(256, 2) gates_gemm(
    int layer, const float* __restrict__ bz, const float* __restrict__ bh)
{
    extern __shared__ __align__(16) char smem_raw[];
    __nv_bfloat16* s = (__nv_bfloat16*)smem_raw;

    const int tid  = threadIdx.x;
    const int lane = tid & 31;
    const int warp = tid >> 5;
    const int wm   = warp >> 2;
    const int wn   = warp & 3;
    const int zsel = blockIdx.x >> 2;
    const int colBase = (blockIdx.x & 3) * BN;
    const size_t rowBase = (size_t)blockIdx.y * BM;

    const __nv_bfloat16* Wh_ = g_Wsp_hi + (((size_t)layer * 2 + zsel) << 18);
    const __nv_bfloat16* Wl_ = g_Wsp_lo + (((size_t)layer * 2 + zsel) << 18);
    const float* bias = zsel ? bh : bz;
    __half*      Out  = zsel ? g_ph : g_kh;

    auto issue = [&](int kt, int st) {
        __nv_bfloat16* sb = s + st * STAGE_EL;
#pragma unroll
        for (int j = 0; j < 4; ++j) {                  // A: 1024 16B chunks
            int i = tid + 256 * j;
            int row = i >> 3, rem = i & 7, hl = rem >> 2, ch = rem & 3;
            const __nv_bfloat16* gsrc = (hl ? g_Al : g_Ah)
                + (rowBase + row) * HID + kt * BK + ch * 8;
            cpasync16(sb + hl * (BM * LDA) + row * LDA + ch * 8, gsrc);
        }
#pragma unroll
        for (int j = 0; j < 4; ++j) {                  // B: 1024 16B chunks
            int i = tid + 256 * j;
            int row = i >> 5, rem = i & 31, hl = rem >> 4, ch = rem & 15;
            const __nv_bfloat16* gsrc = (hl ? Wl_ : Wh_)
                + (size_t)(kt * BK + row) * HID + colBase + ch * 8;
            cpasync16(sb + 2 * BM * LDA + hl * (BK * LDB) + row * LDB + ch * 8, gsrc);
        }
        cp_commit();
    };

    float acc[4][4][4];
#pragma unroll
    for (int mt = 0; mt < 4; ++mt)
#pragma unroll
        for (int nt = 0; nt < 4; ++nt)
#pragma unroll
            for (int r = 0; r < 4; ++r) acc[mt][nt][r] = 0.f;

    auto comp = [&](int st) {
        const __nv_bfloat16* sAh = s + st * STAGE_EL;
        const __nv_bfloat16* sAl = sAh + BM * LDA;
        const __nv_bfloat16* sBh = sAh + 2 * BM * LDA;
        const __nv_bfloat16* sBl = sBh + BK * LDB;
#pragma unroll
        for (int ks = 0; ks < 2; ++ks) {
            uint32_t Bh[4][2], Bl[4][2];
#pragma unroll
            for (int nt = 0; nt < 4; ++nt) {
                int br = ks * 16 + (lane & 15);
                int bc = wn * 32 + nt * 8;
                ldm_x2t(Bh[nt], saddr(sBh + br * LDB + bc));
                ldm_x2t(Bl[nt], saddr(sBl + br * LDB + bc));
            }
#pragma unroll
            for (int mt = 0; mt < 4; ++mt) {
                uint32_t Ah[4], Al[4];
                int ar = wm * 64 + mt * 16 + (lane & 15);
                int ac = ks * 16 + ((lane >> 4) << 3);
                ldm_x4(Ah, saddr(sAh + ar * LDA + ac));
                ldm_x4(Al, saddr(sAl + ar * LDA + ac));
#pragma unroll
                for (int nt = 0; nt < 4; ++nt) {
                    mma16816(acc[mt][nt], Ah, Bh[nt]);
                    mma16816(acc[mt][nt], Ah, Bl[nt]);
                    mma16816(acc[mt][nt], Al, Bh[nt]);
                }
            }
        }
    };

    issue(0, 0);
    const int KI = HID / BK;    // 16
    for (int kt = 0; kt < KI; ++kt) {
        int st = kt & 1;
        cp_wait0();
        __syncthreads();
        if (kt + 1 < KI) issue(kt + 1, st ^ 1);
        comp(st);
    }

#pragma unroll
    for (int mt = 0; mt < 4; ++mt) {
        size_t r0 = rowBase + wm * 64 + mt * 16 + (lane >> 2);
#pragma unroll
        for (int nt = 0; nt < 4; ++nt) {
            int cb = colBase + wn * 32 + nt * 8 + ((lane & 3) << 1);
            float2 bs = *(const float2*)(bias + cb);
            *(__half2*)(Out + r0 * HID + cb) =
                __floats2half2_rn(acc[mt][nt][0] + bs.x, acc[mt][nt][1] + bs.y);
            *(__half2*)(Out + (r0 + 8) * HID + cb) =
                __floats2half2_rn(acc[mt][nt][2] + bs.x, acc[mt][nt][3] + bs.y);
        }
    }
}

// ============================================================================
// Scan summary pass: chunk-level (P, S) only; fp16 k/p, 2 channels/thread.
// grid = BATCH*NC*2 = 4096 blocks x 128 threads, TC=32 steps each.
// ============================================================================
__global__ void __launch_bounds__(128) scan_summary() {
    int b     = blockIdx.x >> 7;                  // NC*2 = 128 blocks per batch
    int chunk = (blockIdx.x >> 1) & (NC - 1);
    int c2    = (blockIdx.x & 1) * 128 + threadIdx.x;   // half2 index 0..255
    size_t base = ((size_t)b * SEQ + chunk * TC) * H2 + c2;

    const __half2* k2g = (const __half2*)g_kh;
    const __half2* p2g = (const __half2*)g_ph;

    float2 S = make_float2(0.f, 0.f), P = make_float2(1.f, 1.f);
#pragma unroll 8
    for (int t = 0; t < TC; ++t) {
        size_t o = base + (size_t)t * H2;
        float2 kv = __half22float2(__ldcs(k2g + o));
        float2 pv = __half22float2(__ldcs(p2g + o));
        float ekx = __expf(-kv.x), eky = __expf(-kv.y);
        float zx  = __fdividef(1.f, 1.f + ekx);
        float zy  = __fdividef(1.f, 1.f + eky);
        float ax  = ekx * zx, ay = eky * zy;
        float gpx = (pv.x >= 0.f) ? (pv.x + 0.5f)
                                  : __fdividef(1.f, 1.f + __expf(-pv.x));
        float gpy = (pv.y >= 0.f) ? (pv.y + 0.5f)
                                  : __fdividef(1.f, 1.f + __expf(-pv.y));
        S.x = fmaf(ax, S.x, zx * gpx);
        S.y = fmaf(ay, S.y, zy * gpy);
        P.x *= ax;
        P.y *= ay;
    }
    ((float2*)g_cA)[(b * NC + chunk) * H2 + c2] = P;
    ((float2*)g_cB)[(b * NC + chunk) * H2 + c2] = S;
}

// ============================================================================
// Chain chunk summaries; emit per-chunk h_in and final hiddens.
// ============================================================================
__global__ void __launch_bounds__(256) scanB(const float* __restrict__ h0l,
                                             float* __restrict__ hid_out) {
    int idx = blockIdx.x * 256 + threadIdx.x;   // 16384
    int b = idx >> 9, c = idx & 511;
    float x0 = h0l[b * HID + c];
    float h = (x0 >= 0.f) ? (x0 + 0.5f)
                          : __fdividef(1.f, 1.f + __expf(-x0));
#pragma unroll
    for (int j = 0; j < NC; ++j) {
        g_hin[(b * NC + j) * HID + c] = h;
        h = fmaf(g_cA[(b * NC + j) * HID + c], h, g_cB[(b * NC + j) * HID + c]);
    }
    hid_out[b * HID + c] = h;
}

// ============================================================================
// Fused scan + LayerNorm + residual (+ bf16 split for next layer's GEMM).
// One block per (b, chunk): 256 threads x 2 channels; fp16 k/p loads.
// ============================================================================
__global__ void __launch_bounds__(256, 2) scan_ln(const float* __restrict__ resid,
                                                  const float* __restrict__ gamma,
                                                  const float* __restrict__ beta,
                                                  float* __restrict__ outp,
                                                  int write_split) {
    __shared__ float red[8][16];      // [warp][8 x s, 8 x s2]
    __shared__ float bcast[2][STEP];  // [mu | rstd][step]
    int b = blockIdx.x >> 6, chunk = blockIdx.x & (NC - 1);
    int c2 = threadIdx.x, lane = c2 & 31, warp = c2 >> 5;

    float2 h   = ((const float2*)g_hin)[(b * NC + chunk) * H2 + c2];
    float2 gm  = __ldg((const float2*)gamma + c2);
    float2 bt  = __ldg((const float2*)beta + c2);
    size_t base2 = ((size_t)b * SEQ + chunk * TC) * H2 + c2;   // pair index

    const __half2* k2g = (const __half2*)g_kh;
    const __half2* p2g = (const __half2*)g_ph;
    const float2*  r2g = (const float2*)resid;
    float2*        o2g = (float2*)outp;

    for (int t0 = 0; t0 < TC; t0 += STEP) {
        float2 k8[STEP], p8[STEP], r8[STEP], h8[STEP];
        float s8[STEP], q8[STEP];
#pragma unroll
        for (int j = 0; j < STEP; ++j) {          // batched loads (MLP ~24)
            size_t o = base2 + (size_t)(t0 + j) * H2;
            k8[j] = __half22float2(__ldcs(k2g + o));
            p8[j] = __half22float2(__ldcs(p2g + o));
            r8[j] = __ldg(r2g + o);
        }
#pragma unroll
        for (int j = 0; j < STEP; ++j) {          // 8-step h chain (2 ch)
            float ekx = __expf(-k8[j].x), eky = __expf(-k8[j].y);
            float zx  = __fdividef(1.f, 1.f + ekx);
            float zy  = __fdividef(1.f, 1.f + eky);
            float ax  = ekx * zx, ay = eky * zy;
            float gpx = (p8[j].x >= 0.f) ? (p8[j].x + 0.5f)
                                         : __fdividef(1.f, 1.f + __expf(-p8[j].x));
            float gpy = (p8[j].y >= 0.f) ? (p8[j].y + 0.5f)
                                         : __fdividef(1.f, 1.f + __expf(-p8[j].y));
            h.x = fmaf(ax, h.x, zx * gpx);
            h.y = fmaf(ay, h.y, zy * gpy);
            h8[j] = h;
            s8[j] = h.x + h.y;
            q8[j] = h.x * h.x + h.y * h.y;
        }
        // warp butterfly: 16 independent reductions, full ILP
#pragma unroll
        for (int off = 16; off; off >>= 1) {
#pragma unroll
            for (int j = 0; j < STEP; ++j) {
                s8[j] += __shfl_xor_sync(0xffffffffu, s8[j], off);
                q8[j] += __shfl_xor_sync(0xffffffffu, q8[j], off);
            }
        }
        if (lane == 0) {
#pragma unroll
            for (int j = 0; j < STEP; ++j) {
                red[warp][j]        = s8[j];
                red[warp][j + STEP] = q8[j];
            }
        }
        __syncthreads();
        if (warp == 0) {
            float v = 0.f;
            if (lane < 16) {
#pragma unroll
                for (int w = 0; w < 8; ++w) v += red[w][lane];
            }
            float vq = __shfl_down_sync(0xffffffffu, v, STEP);
            if (lane < STEP) {
                float mu  = v * (1.f / HID);
                float var = fmaf(vq, 1.f / HID, -mu * mu);
                bcast[0][lane] = mu;
                bcast[1][lane] = rsqrtf(var + 1e-5f);
            }
        }
        __syncthreads();
#pragma unroll
        for (int j = 0; j < STEP; ++j) {
            size_t o = base2 + (size_t)(t0 + j) * H2;
            float mu = bcast[0][j], rstd = bcast[1][j];
            float2 ov;
            ov.x = (h8[j].x - mu) * rstd * gm.x + bt.x + r8[j].x;
            ov.y = (h8[j].y - mu) * rstd * gm.y + bt.y + r8[j].y;
            o2g[o] = ov;
            if (write_split)
                split2(ov.x, ov.y, g_Ah + 2 * o, g_Al + 2 * o);
        }
    }
}

// ============================================================================
extern "C" void kernel_launch(void* const* d_in, const int* in_sizes, int n_in,
                              void* d_out, int out_size)
{
    const float* x     = (const float*)d_in[0];
    const float* h0    = (const float*)d_in[1];
    const float* Wz    = (const float*)d_in[2];
    const float* bz    = (const float*)d_in[3];
    const float* Wh    = (const float*)d_in[4];
    const float* bh    = (const float*)d_in[5];
    const float* gamma = (const float*)d_in[6];
    const float* beta  = (const float*)d_in[7];

    float* out_cur = (float*)d_out;                       // (B, T, H)
    float* out_hid = out_cur + (size_t)MTOT * HID;        // (L, B, H)

    cudaFuncSetAttribute(gates_gemm,
                         cudaFuncAttributeMaxDynamicSharedMemorySize, SMEM_BYTES);

    split_w<<<(NLAYERS * HID * HID) / 256, 256>>>(Wz, Wh);
    split_x<<<(MTOT * HID / 2) / 256, 256>>>(x);

    const float* cur = x;
    for (int i = 0; i < NLAYERS; ++i) {
        gates_gemm<<<dim3(8, MTOT / BM), 256, SMEM_BYTES>>>(
            i, bz + i * HID, bh + i * HID);
        scan_summary<<<BATCH * NC * 2, 128>>>();
        scanB<<<64, 256>>>(h0 + (size_t)i * BATCH * HID,
                           out_hid + (size_t)i * BATCH * HID);
        scan_ln<<<BATCH * NC, 256>>>(cur, gamma + i * HID, beta + i * HID,
                                     out_cur, (i < NLAYERS - 1) ? 1 : 0);
        cur = out_cur;
    }
}

// round 8
// speedup vs baseline: 1.9759x; 1.7161x over previous
#include <cuda_runtime.h>
#include <cuda_bf16.h>
#include <cuda_fp16.h>
#include <cstdint>

#define NLAYERS 4
#define HID 512
#define BATCH 32
#define SEQ 2048
#define MTOT (BATCH*SEQ)          // 65536
#define NC 64                     // scan chunks
#define TC (SEQ/NC)               // 32 steps per chunk
#define STEP 8                    // timesteps per reduction round in scan_ln
#define H2 (HID/2)                // 256 channel-pairs per row

// ---------------- GEMM tiling ----------------
#define BM 128
#define BN 128
#define BK 32
#define LDA 40                    // BK + 8 pad (row = 80B)
#define LDB 136                   // BN + 8 pad (row = 272B)
#define STAGE_EL (BM*LDA + BK*LDB)                // 9472 fp16
#define SMEM_BYTES (2*STAGE_EL*2)                 // 37888 bytes

// ---------------- scratch ----------------
__device__ __half g_kh[(size_t)MTOT * HID];       // z-gate pre-activation (fp16)
__device__ __half g_ph[(size_t)MTOT * HID];       // h~ pre-activation (fp16)
__device__ __half g_Af[(size_t)MTOT * HID];       // activations (fp16)
__device__ __half g_Wf[(size_t)NLAYERS * 2 * HID * HID];  // weights (fp16)
__device__ float g_cA[BATCH * NC * HID];
__device__ float g_cB[BATCH * NC * HID];
__device__ float g_hin[BATCH * NC * HID];

// ---------------- helpers ----------------
__device__ __forceinline__ uint32_t saddr(const void* p) {
    return (uint32_t)__cvta_generic_to_shared(p);
}
__device__ __forceinline__ void cpasync16(void* smem, const void* g) {
    asm volatile("cp.async.cg.shared.global [%0], [%1], 16;"
                 :: "r"(saddr(smem)), "l"(g));
}
__device__ __forceinline__ void cp_commit() {
    asm volatile("cp.async.commit_group;");
}
__device__ __forceinline__ void cp_wait0() {
    asm volatile("cp.async.wait_group 0;");
}
__device__ __forceinline__ void ldm_x4(uint32_t* r, uint32_t a) {
    asm volatile("ldmatrix.sync.aligned.m8n8.x4.shared.b16 {%0,%1,%2,%3}, [%4];"
                 : "=r"(r[0]), "=r"(r[1]), "=r"(r[2]), "=r"(r[3]) : "r"(a));
}
__device__ __forceinline__ void ldm_x2t(uint32_t* r, uint32_t a) {
    asm volatile("ldmatrix.sync.aligned.m8n8.x2.trans.shared.b16 {%0,%1}, [%2];"
                 : "=r"(r[0]), "=r"(r[1]) : "r"(a));
}
__device__ __forceinline__ void mma16816(float* c, const uint32_t* a, const uint32_t* b) {
    asm volatile(
        "mma.sync.aligned.m16n8k16.row.col.f32.f16.f16.f32 "
        "{%0,%1,%2,%3}, {%4,%5,%6,%7}, {%8,%9}, {%0,%1,%2,%3};"
        : "+f"(c[0]), "+f"(c[1]), "+f"(c[2]), "+f"(c[3])
        : "r"(a[0]), "r"(a[1]), "r"(a[2]), "r"(a[3]), "r"(b[0]), "r"(b[1]));
}

// ============================================================================
// One-shot conversion kernels
// ============================================================================
__global__ void __launch_bounds__(256) conv_w(const float* __restrict__ Wz,
                                              const float* __restrict__ Wh) {
    size_t i = (size_t)blockIdx.x * 256 + threadIdx.x;    // over 4*512*512
    size_t l = i >> 18, r = i & ((1u << 18) - 1);
    g_Wf[((l * 2 + 0) << 18) + r] = __float2half_rn(Wz[i]);
    g_Wf[((l * 2 + 1) << 18) + r] = __float2half_rn(Wh[i]);
}

__global__ void __launch_bounds__(256) conv_x(const float* __restrict__ x) {
    size_t i = (size_t)blockIdx.x * 256 + threadIdx.x;    // over MTOT*HID/2
    float2 v = ((const float2*)x)[i];
    ((__half2*)g_Af)[i] = __floats2half2_rn(v.x, v.y);
}

// ============================================================================
// Fused dual GEMM, single-pass fp16 operands, fp32 accumulate, fp16 output.
// grid = (8, MTOT/128): blockIdx.x = {4 n-tiles} x {z / h}.
// ============================================================================
__global__ void __launch_bounds__(256, 2) gates_gemm(
    int layer, const float* __restrict__ bz, const float* __restrict__ bh)
{
    extern __shared__ __align__(16) char smem_raw[];
    __half* s = (__half*)smem_raw;

    const int tid  = threadIdx.x;
    const int lane = tid & 31;
    const int warp = tid >> 5;
    const int wm   = warp >> 2;
    const int wn   = warp & 3;
    const int zsel = blockIdx.x >> 2;
    const int colBase = (blockIdx.x & 3) * BN;
    const size_t rowBase = (size_t)blockIdx.y * BM;

    const __half* W_   = g_Wf + (((size_t)layer * 2 + zsel) << 18);
    const float* bias  = zsel ? bh : bz;
    __half*      Out   = zsel ? g_ph : g_kh;

    auto issue = [&](int kt, int st) {
        __half* sb = s + st * STAGE_EL;
        {   // A: 512 chunks of 16B (4 per row), 2 per thread
#pragma unroll
            for (int j = 0; j < 2; ++j) {
                int i = tid + 256 * j;
                int row = i >> 2, ch = i & 3;
                const __half* gsrc = g_Af + (rowBase + row) * HID + kt * BK + ch * 8;
                cpasync16(sb + row * LDA + ch * 8, gsrc);
            }
        }
        {   // B: 512 chunks of 16B (16 per row), 2 per thread
#pragma unroll
            for (int j = 0; j < 2; ++j) {
                int i = tid + 256 * j;
                int row = i >> 4, ch = i & 15;
                const __half* gsrc = W_ + (size_t)(kt * BK + row) * HID + colBase + ch * 8;
                cpasync16(sb + BM * LDA + row * LDB + ch * 8, gsrc);
            }
        }
        cp_commit();
    };

    float acc[4][4][4];
#pragma unroll
    for (int mt = 0; mt < 4; ++mt)
#pragma unroll
        for (int nt = 0; nt < 4; ++nt)
#pragma unroll
            for (int r = 0; r < 4; ++r) acc[mt][nt][r] = 0.f;

    auto comp = [&](int st) {
        const __half* sA = s + st * STAGE_EL;
        const __half* sB = sA + BM * LDA;
#pragma unroll
        for (int ks = 0; ks < 2; ++ks) {
            uint32_t B[4][2];
#pragma unroll
            for (int nt = 0; nt < 4; ++nt) {
                int br = ks * 16 + (lane & 15);
                int bc = wn * 32 + nt * 8;
                ldm_x2t(B[nt], saddr(sB + br * LDB + bc));
            }
#pragma unroll
            for (int mt = 0; mt < 4; ++mt) {
                uint32_t A[4];
                int ar = wm * 64 + mt * 16 + (lane & 15);
                int ac = ks * 16 + ((lane >> 4) << 3);
                ldm_x4(A, saddr(sA + ar * LDA + ac));
#pragma unroll
                for (int nt = 0; nt < 4; ++nt)
                    mma16816(acc[mt][nt], A, B[nt]);
            }
        }
    };

    issue(0, 0);
    const int KI = HID / BK;    // 16
    for (int kt = 0; kt < KI; ++kt) {
        int st = kt & 1;
        cp_wait0();
        __syncthreads();
        if (kt + 1 < KI) issue(kt + 1, st ^ 1);
        comp(st);
    }

#pragma unroll
    for (int mt = 0; mt < 4; ++mt) {
        size_t r0 = rowBase + wm * 64 + mt * 16 + (lane >> 2);
#pragma unroll
        for (int nt = 0; nt < 4; ++nt) {
            int cb = colBase + wn * 32 + nt * 8 + ((lane & 3) << 1);
            float2 bs = *(const float2*)(bias + cb);
            *(__half2*)(Out + r0 * HID + cb) =
                __floats2half2_rn(acc[mt][nt][0] + bs.x, acc[mt][nt][1] + bs.y);
            *(__half2*)(Out + (r0 + 8) * HID + cb) =
                __floats2half2_rn(acc[mt][nt][2] + bs.x, acc[mt][nt][3] + bs.y);
        }
    }
}

// ============================================================================
// Scan summary pass: chunk-level (P, S) only; fp16 k/p, 2 channels/thread.
// grid = BATCH*NC*2 = 4096 blocks x 128 threads, TC=32 steps each.
// ============================================================================
__global__ void __launch_bounds__(128) scan_summary() {
    int b     = blockIdx.x >> 7;                  // NC*2 = 128 blocks per batch
    int chunk = (blockIdx.x >> 1) & (NC - 1);
    int c2    = (blockIdx.x & 1) * 128 + threadIdx.x;   // half2 index 0..255
    size_t base = ((size_t)b * SEQ + chunk * TC) * H2 + c2;

    const __half2* k2g = (const __half2*)g_kh;
    const __half2* p2g = (const __half2*)g_ph;

    float2 S = make_float2(0.f, 0.f), P = make_float2(1.f, 1.f);
#pragma unroll 8
    for (int t = 0; t < TC; ++t) {
        size_t o = base + (size_t)t * H2;
        float2 kv = __half22float2(__ldcs(k2g + o));
        float2 pv = __half22float2(__ldcs(p2g + o));
        float ekx = __expf(-kv.x), eky = __expf(-kv.y);
        float zx  = __fdividef(1.f, 1.f + ekx);
        float zy  = __fdividef(1.f, 1.f + eky);
        float ax  = ekx * zx, ay = eky * zy;
        float gpx = (pv.x >= 0.f) ? (pv.x + 0.5f)
                                  : __fdividef(1.f, 1.f + __expf(-pv.x));
        float gpy = (pv.y >= 0.f) ? (pv.y + 0.5f)
                                  : __fdividef(1.f, 1.f + __expf(-pv.y));
        S.x = fmaf(ax, S.x, zx * gpx);
        S.y = fmaf(ay, S.y, zy * gpy);
        P.x *= ax;
        P.y *= ay;
    }
    ((float2*)g_cA)[(b * NC + chunk) * H2 + c2] = P;
    ((float2*)g_cB)[(b * NC + chunk) * H2 + c2] = S;
}

// ============================================================================
// Chain chunk summaries; emit per-chunk h_in and final hiddens.
// ============================================================================
__global__ void __launch_bounds__(256) scanB(const float* __restrict__ h0l,
                                             float* __restrict__ hid_out) {
    int idx = blockIdx.x * 256 + threadIdx.x;   // 16384
    int b = idx >> 9, c = idx & 511;
    float x0 = h0l[b * HID + c];
    float h = (x0 >= 0.f) ? (x0 + 0.5f)
                          : __fdividef(1.f, 1.f + __expf(-x0));
#pragma unroll
    for (int j = 0; j < NC; ++j) {
        g_hin[(b * NC + j) * HID + c] = h;
        h = fmaf(g_cA[(b * NC + j) * HID + c], h, g_cB[(b * NC + j) * HID + c]);
    }
    hid_out[b * HID + c] = h;
}

// ============================================================================
// Fused scan + LayerNorm + residual (+ fp16 activation write for next layer).
// One block per (b, chunk): 256 threads x 2 channels; fp16 k/p loads.
// ============================================================================
__global__ void __launch_bounds__(256, 2) scan_ln(const float* __restrict__ resid,
                                                  const float* __restrict__ gamma,
                                                  const float* __restrict__ beta,
                                                  float* __restrict__ outp,
                                                  int write_split) {
    __shared__ float red[8][16];      // [warp][8 x s, 8 x s2]
    __shared__ float bcast[2][STEP];  // [mu | rstd][step]
    int b = blockIdx.x >> 6, chunk = blockIdx.x & (NC - 1);
    int c2 = threadIdx.x, lane = c2 & 31, warp = c2 >> 5;

    float2 h   = ((const float2*)g_hin)[(b * NC + chunk) * H2 + c2];
    float2 gm  = __ldg((const float2*)gamma + c2);
    float2 bt  = __ldg((const float2*)beta + c2);
    size_t base2 = ((size_t)b * SEQ + chunk * TC) * H2 + c2;   // pair index

    const __half2* k2g = (const __half2*)g_kh;
    const __half2* p2g = (const __half2*)g_ph;
    const float2*  r2g = (const float2*)resid;
    float2*        o2g = (float2*)outp;
    __half2*       a2g = (__half2*)g_Af;

    for (int t0 = 0; t0 < TC; t0 += STEP) {
        float2 k8[STEP], p8[STEP], r8[STEP], h8[STEP];
        float s8[STEP], q8[STEP];
#pragma unroll
        for (int j = 0; j < STEP; ++j) {          // batched loads (MLP ~24)
            size_t o = base2 + (size_t)(t0 + j) * H2;
            k8[j] = __half22float2(__ldcs(k2g + o));
            p8[j] = __half22float2(__ldcs(p2g + o));
            r8[j] = __ldg(r2g + o);
        }
#pragma unroll
        for (int j = 0; j < STEP; ++j) {          // 8-step h chain (2 ch)
            float ekx = __expf(-k8[j].x), eky = __expf(-k8[j].y);
            float zx  = __fdividef(1.f, 1.f + ekx);
            float zy  = __fdividef(1.f, 1.f + eky);
            float ax  = ekx * zx, ay = eky * zy;
            float gpx = (p8[j].x >= 0.f) ? (p8[j].x + 0.5f)
                                         : __fdividef(1.f, 1.f + __expf(-p8[j].x));
            float gpy = (p8[j].y >= 0.f) ? (p8[j].y + 0.5f)
                                         : __fdividef(1.f, 1.f + __expf(-p8[j].y));
            h.x = fmaf(ax, h.x, zx * gpx);
            h.y = fmaf(ay, h.y, zy * gpy);
            h8[j] = h;
            s8[j] = h.x + h.y;
            q8[j] = h.x * h.x + h.y * h.y;
        }
        // warp butterfly: 16 independent reductions, full ILP
#pragma unroll
        for (int off = 16; off; off >>= 1) {
#pragma unroll
            for (int j = 0; j < STEP; ++j) {
                s8[j] += __shfl_xor_sync(0xffffffffu, s8[j], off);
                q8[j] += __shfl_xor_sync(0xffffffffu, q8[j], off);
            }
        }
        if (lane == 0) {
#pragma unroll
            for (int j = 0; j < STEP; ++j) {
                red[warp][j]        = s8[j];
                red[warp][j + STEP] = q8[j];
            }
        }
        __syncthreads();
        if (warp == 0) {
            float v = 0.f;
            if (lane < 16) {
#pragma unroll
                for (int w = 0; w < 8; ++w) v += red[w][lane];
            }
            float vq = __shfl_down_sync(0xffffffffu, v, STEP);
            if (lane < STEP) {
                float mu  = v * (1.f / HID);
                float var = fmaf(vq, 1.f / HID, -mu * mu);
                bcast[0][lane] = mu;
                bcast[1][lane] = rsqrtf(var + 1e-5f);
            }
        }
        __syncthreads();
#pragma unroll
        for (int j = 0; j < STEP; ++j) {
            size_t o = base2 + (size_t)(t0 + j) * H2;
            float mu = bcast[0][j], rstd = bcast[1][j];
            float2 ov;
            ov.x = (h8[j].x - mu) * rstd * gm.x + bt.x + r8[j].x;
            ov.y = (h8[j].y - mu) * rstd * gm.y + bt.y + r8[j].y;
            o2g[o] = ov;
            if (write_split)
                a2g[o] = __floats2half2_rn(ov.x, ov.y);
        }
    }
}

// ============================================================================
extern "C" void kernel_launch(void* const* d_in, const int* in_sizes, int n_in,
                              void* d_out, int out_size)
{
    const float* x     = (const float*)d_in[0];
    const float* h0    = (const float*)d_in[1];
    const float* Wz    = (const float*)d_in[2];
    const float* bz    = (const float*)d_in[3];
    const float* Wh    = (const float*)d_in[4];
    const float* bh    = (const float*)d_in[5];
    const float* gamma = (const float*)d_in[6];
    const float* beta  = (const float*)d_in[7];

    float* out_cur = (float*)d_out;                       // (B, T, H)
    float* out_hid = out_cur + (size_t)MTOT * HID;        // (L, B, H)

    conv_w<<<(NLAYERS * HID * HID) / 256, 256>>>(Wz, Wh);
    conv_x<<<(MTOT * HID / 2) / 256, 256>>>(x);

    const float* cur = x;
    for (int i = 0; i < NLAYERS; ++i) {
        gates_gemm<<<dim3(8, MTOT / BM), 256, SMEM_BYTES>>>(
            i, bz + i * HID, bh + i * HID);
        scan_summary<<<BATCH * NC * 2, 128>>>();
        scanB<<<64, 256>>>(h0 + (size_t)i * BATCH * HID,
                           out_hid + (size_t)i * BATCH * HID);
        scan_ln<<<BATCH * NC, 256>>>(cur, gamma + i * HID, beta + i * HID,
                                     out_cur, (i < NLAYERS - 1) ? 1 : 0);
        cur = out_cur;
    }
}

// round 9
// speedup vs baseline: 2.0265x; 1.0256x over previous
#include <cuda_runtime.h>
#include <cuda_bf16.h>
#include <cuda_fp16.h>
#include <cstdint>

#define NLAYERS 4
#define HID 512
#define BATCH 32
#define SEQ 2048
#define MTOT (BATCH*SEQ)          // 65536
#define NC 64                     // scan chunks
#define TC (SEQ/NC)               // 32 steps per chunk
#define STEP 8                    // timesteps per reduction round in scan_ln
#define H2 (HID/2)                // 256 channel-pairs per row

// ---------------- GEMM tiling ----------------
#define BM 128
#define BN 128
#define BK 32
#define LDA 40                    // BK + 8 pad (row = 80B)
#define LDB 136                   // BN + 8 pad (row = 272B)
#define STAGE_EL (BM*LDA + BK*LDB)                // 9472 fp16
#define SMEM_BYTES (2*STAGE_EL*2)                 // 37888 bytes

// ---------------- scratch ----------------
__device__ __half g_kh[(size_t)MTOT * HID];       // z-gate pre-activation (fp16)
__device__ __half g_ph[(size_t)MTOT * HID];       // h~ pre-activation (fp16)
__device__ __half g_Af[(size_t)MTOT * HID];       // activations (fp16)
__device__ __half g_Wf[(size_t)NLAYERS * 2 * HID * HID];  // weights (fp16)
__device__ float g_cA[BATCH * NC * HID];
__device__ float g_cB[BATCH * NC * HID];
__device__ float g_hin[BATCH * NC * HID];

// ---------------- helpers ----------------
__device__ __forceinline__ uint32_t saddr(const void* p) {
    return (uint32_t)__cvta_generic_to_shared(p);
}
__device__ __forceinline__ void cpasync16(void* smem, const void* g) {
    asm volatile("cp.async.cg.shared.global [%0], [%1], 16;"
                 :: "r"(saddr(smem)), "l"(g));
}
__device__ __forceinline__ void cp_commit() {
    asm volatile("cp.async.commit_group;");
}
__device__ __forceinline__ void cp_wait0() {
    asm volatile("cp.async.wait_group 0;");
}
__device__ __forceinline__ void ldm_x4(uint32_t* r, uint32_t a) {
    asm volatile("ldmatrix.sync.aligned.m8n8.x4.shared.b16 {%0,%1,%2,%3}, [%4];"
                 : "=r"(r[0]), "=r"(r[1]), "=r"(r[2]), "=r"(r[3]) : "r"(a));
}
__device__ __forceinline__ void ldm_x2t(uint32_t* r, uint32_t a) {
    asm volatile("ldmatrix.sync.aligned.m8n8.x2.trans.shared.b16 {%0,%1}, [%2];"
                 : "=r"(r[0]), "=r"(r[1]) : "r"(a));
}
__device__ __forceinline__ void mma16816(float* c, const uint32_t* a, const uint32_t* b) {
    asm volatile(
        "mma.sync.aligned.m16n8k16.row.col.f32.f16.f16.f32 "
        "{%0,%1,%2,%3}, {%4,%5,%6,%7}, {%8,%9}, {%0,%1,%2,%3};"
        : "+f"(c[0]), "+f"(c[1]), "+f"(c[2]), "+f"(c[3])
        : "r"(a[0]), "r"(a[1]), "r"(a[2]), "r"(a[3]), "r"(b[0]), "r"(b[1]));
}

// ============================================================================
// One-shot conversion kernels
// ============================================================================
__global__ void __launch_bounds__(256) conv_w(const float* __restrict__ Wz,
                                              const float* __restrict__ Wh) {
    size_t i = (size_t)blockIdx.x * 256 + threadIdx.x;    // over 4*512*512
    size_t l = i >> 18, r = i & ((1u << 18) - 1);
    g_Wf[((l * 2 + 0) << 18) + r] = __float2half_rn(Wz[i]);
    g_Wf[((l * 2 + 1) << 18) + r] = __float2half_rn(Wh[i]);
}

__global__ void __launch_bounds__(256) conv_x(const float* __restrict__ x) {
    size_t i = (size_t)blockIdx.x * 256 + threadIdx.x;    // over MTOT*HID/2
    float2 v = ((const float2*)x)[i];
    ((__half2*)g_Af)[i] = __floats2half2_rn(v.x, v.y);
}

// ============================================================================
// Fused dual GEMM, single-pass fp16 operands, fp32 accumulate, fp16 output.
// grid = (8, MTOT/128): blockIdx.x = {4 n-tiles} x {z / h}.
// ============================================================================
__global__ void __launch_bounds__(256, 2) gates_gemm(
    int layer, const float* __restrict__ bz, const float* __restrict__ bh)
{
    extern __shared__ __align__(16) char smem_raw[];
    __half* s = (__half*)smem_raw;

    const int tid  = threadIdx.x;
    const int lane = tid & 31;
    const int warp = tid >> 5;
    const int wm   = warp >> 2;
    const int wn   = warp & 3;
    const int zsel = blockIdx.x >> 2;
    const int colBase = (blockIdx.x & 3) * BN;
    const size_t rowBase = (size_t)blockIdx.y * BM;

    const __half* W_   = g_Wf + (((size_t)layer * 2 + zsel) << 18);
    const float* bias  = zsel ? bh : bz;
    __half*      Out   = zsel ? g_ph : g_kh;

    auto issue = [&](int kt, int st) {
        __half* sb = s + st * STAGE_EL;
        {   // A: 512 chunks of 16B (4 per row), 2 per thread
#pragma unroll
            for (int j = 0; j < 2; ++j) {
                int i = tid + 256 * j;
                int row = i >> 2, ch = i & 3;
                const __half* gsrc = g_Af + (rowBase + row) * HID + kt * BK + ch * 8;
                cpasync16(sb + row * LDA + ch * 8, gsrc);
            }
        }
        {   // B: 512 chunks of 16B (16 per row), 2 per thread
#pragma unroll
            for (int j = 0; j < 2; ++j) {
                int i = tid + 256 * j;
                int row = i >> 4, ch = i & 15;
                const __half* gsrc = W_ + (size_t)(kt * BK + row) * HID + colBase + ch * 8;
                cpasync16(sb + BM * LDA + row * LDB + ch * 8, gsrc);
            }
        }
        cp_commit();
    };

    float acc[4][4][4];
#pragma unroll
    for (int mt = 0; mt < 4; ++mt)
#pragma unroll
        for (int nt = 0; nt < 4; ++nt)
#pragma unroll
            for (int r = 0; r < 4; ++r) acc[mt][nt][r] = 0.f;

    auto comp = [&](int st) {
        const __half* sA = s + st * STAGE_EL;
        const __half* sB = sA + BM * LDA;
#pragma unroll
        for (int ks = 0; ks < 2; ++ks) {
            uint32_t B[4][2];
#pragma unroll
            for (int nt = 0; nt < 4; ++nt) {
                int br = ks * 16 + (lane & 15);
                int bc = wn * 32 + nt * 8;
                ldm_x2t(B[nt], saddr(sB + br * LDB + bc));
            }
#pragma unroll
            for (int mt = 0; mt < 4; ++mt) {
                uint32_t A[4];
                int ar = wm * 64 + mt * 16 + (lane & 15);
                int ac = ks * 16 + ((lane >> 4) << 3);
                ldm_x4(A, saddr(sA + ar * LDA + ac));
#pragma unroll
                for (int nt = 0; nt < 4; ++nt)
                    mma16816(acc[mt][nt], A, B[nt]);
            }
        }
    };

    issue(0, 0);
    const int KI = HID / BK;    // 16
    for (int kt = 0; kt < KI; ++kt) {
        int st = kt & 1;
        cp_wait0();
        __syncthreads();
        if (kt + 1 < KI) issue(kt + 1, st ^ 1);
        comp(st);
    }

#pragma unroll
    for (int mt = 0; mt < 4; ++mt) {
        size_t r0 = rowBase + wm * 64 + mt * 16 + (lane >> 2);
#pragma unroll
        for (int nt = 0; nt < 4; ++nt) {
            int cb = colBase + wn * 32 + nt * 8 + ((lane & 3) << 1);
            float2 bs = *(const float2*)(bias + cb);
            *(__half2*)(Out + r0 * HID + cb) =
                __floats2half2_rn(acc[mt][nt][0] + bs.x, acc[mt][nt][1] + bs.y);
            *(__half2*)(Out + (r0 + 8) * HID + cb) =
                __floats2half2_rn(acc[mt][nt][2] + bs.x, acc[mt][nt][3] + bs.y);
        }
    }
}

// ============================================================================
// Scan summary pass: chunk-level (P, S) only; fp16 k/p, 2 channels/thread.
// grid = BATCH*NC*2 = 4096 blocks x 128 threads, TC=32 steps each.
// ============================================================================
__global__ void __launch_bounds__(128) scan_summary() {
    int b     = blockIdx.x >> 7;                  // NC*2 = 128 blocks per batch
    int chunk = (blockIdx.x >> 1) & (NC - 1);
    int c2    = (blockIdx.x & 1) * 128 + threadIdx.x;   // half2 index 0..255
    size_t base = ((size_t)b * SEQ + chunk * TC) * H2 + c2;

    const __half2* k2g = (const __half2*)g_kh;
    const __half2* p2g = (const __half2*)g_ph;

    float2 S = make_float2(0.f, 0.f), P = make_float2(1.f, 1.f);
#pragma unroll 8
    for (int t = 0; t < TC; ++t) {
        size_t o = base + (size_t)t * H2;
        float2 kv = __half22float2(__ldcs(k2g + o));
        float2 pv = __half22float2(__ldcs(p2g + o));
        float ekx = __expf(-kv.x), eky = __expf(-kv.y);
        float zx  = __fdividef(1.f, 1.f + ekx);
        float zy  = __fdividef(1.f, 1.f + eky);
        float ax  = ekx * zx, ay = eky * zy;
        float gpx = (pv.x >= 0.f) ? (pv.x + 0.5f)
                                  : __fdividef(1.f, 1.f + __expf(-pv.x));
        float gpy = (pv.y >= 0.f) ? (pv.y + 0.5f)
                                  : __fdividef(1.f, 1.f + __expf(-pv.y));
        S.x = fmaf(ax, S.x, zx * gpx);
        S.y = fmaf(ay, S.y, zy * gpy);
        P.x *= ax;
        P.y *= ay;
    }
    ((float2*)g_cA)[(b * NC + chunk) * H2 + c2] = P;
    ((float2*)g_cB)[(b * NC + chunk) * H2 + c2] = S;
}

// ============================================================================
// Chain chunk summaries; emit per-chunk h_in and final hiddens.
// ============================================================================
__global__ void __launch_bounds__(256) scanB(const float* __restrict__ h0l,
                                             float* __restrict__ hid_out) {
    int idx = blockIdx.x * 256 + threadIdx.x;   // 16384
    int b = idx >> 9, c = idx & 511;
    float x0 = h0l[b * HID + c];
    float h = (x0 >= 0.f) ? (x0 + 0.5f)
                          : __fdividef(1.f, 1.f + __expf(-x0));
#pragma unroll
    for (int j = 0; j < NC; ++j) {
        g_hin[(b * NC + j) * HID + c] = h;
        h = fmaf(g_cA[(b * NC + j) * HID + c], h, g_cB[(b * NC + j) * HID + c]);
    }
    hid_out[b * HID + c] = h;
}

// ============================================================================
// Fused scan + LayerNorm + residual (+ fp16 activation write for next layer).
// One block per (b, chunk): 256 threads x 2 channels; fp16 k/p loads.
// Software-pipelined across STEP-rounds: next round's 24 loads are issued
// before this round's reduction, hiding DRAM latency behind shfl/barrier work.
// ============================================================================
__global__ void __launch_bounds__(256, 2) scan_ln(const float* __restrict__ resid,
                                                  const float* __restrict__ gamma,
                                                  const float* __restrict__ beta,
                                                  float* __restrict__ outp,
                                                  int write_split) {
    __shared__ float red[8][16];      // [warp][8 x s, 8 x s2]
    __shared__ float bcast[2][STEP];  // [mu | rstd][step]
    int b = blockIdx.x >> 6, chunk = blockIdx.x & (NC - 1);
    int c2 = threadIdx.x, lane = c2 & 31, warp = c2 >> 5;

    float2 h   = ((const float2*)g_hin)[(b * NC + chunk) * H2 + c2];
    float2 gm  = __ldg((const float2*)gamma + c2);
    float2 bt  = __ldg((const float2*)beta + c2);
    size_t base2 = ((size_t)b * SEQ + chunk * TC) * H2 + c2;   // pair index

    const __half2* k2g = (const __half2*)g_kh;
    const __half2* p2g = (const __half2*)g_ph;
    const float2*  r2g = (const float2*)resid;
    float2*        o2g = (float2*)outp;
    __half2*       a2g = (__half2*)g_Af;

    __half2 kc[STEP], pc[STEP];
    float2  rc[STEP];
#pragma unroll
    for (int j = 0; j < STEP; ++j) {              // prologue loads (round 0)
        size_t o = base2 + (size_t)j * H2;
        kc[j] = __ldcs(k2g + o);
        pc[j] = __ldcs(p2g + o);
        rc[j] = __ldcs(r2g + o);
    }

#pragma unroll
    for (int t0 = 0; t0 < TC; t0 += STEP) {
        float2 h8[STEP];
        float s8[STEP], q8[STEP];
#pragma unroll
        for (int j = 0; j < STEP; ++j) {          // 8-step h chain (2 ch)
            float2 kv = __half22float2(kc[j]);
            float2 pv = __half22float2(pc[j]);
            float ekx = __expf(-kv.x), eky = __expf(-kv.y);
            float zx  = __fdividef(1.f, 1.f + ekx);
            float zy  = __fdividef(1.f, 1.f + eky);
            float ax  = ekx * zx, ay = eky * zy;
            float gpx = (pv.x >= 0.f) ? (pv.x + 0.5f)
                                      : __fdividef(1.f, 1.f + __expf(-pv.x));
            float gpy = (pv.y >= 0.f) ? (pv.y + 0.5f)
                                      : __fdividef(1.f, 1.f + __expf(-pv.y));
            h.x = fmaf(ax, h.x, zx * gpx);
            h.y = fmaf(ay, h.y, zy * gpy);
            h8[j] = h;
            s8[j] = h.x + h.y;
            q8[j] = h.x * h.x + h.y * h.y;
        }
        float2 r8[STEP];
#pragma unroll
        for (int j = 0; j < STEP; ++j) r8[j] = rc[j];

        // prefetch next round while the reduction runs
        if (t0 + STEP < TC) {
#pragma unroll
            for (int j = 0; j < STEP; ++j) {
                size_t o = base2 + (size_t)(t0 + STEP + j) * H2;
                kc[j] = __ldcs(k2g + o);
                pc[j] = __ldcs(p2g + o);
                rc[j] = __ldcs(r2g + o);
            }
        }

        // warp butterfly: 16 independent reductions, full ILP
#pragma unroll
        for (int off = 16; off; off >>= 1) {
#pragma unroll
            for (int j = 0; j < STEP; ++j) {
                s8[j] += __shfl_xor_sync(0xffffffffu, s8[j], off);
                q8[j] += __shfl_xor_sync(0xffffffffu, q8[j], off);
            }
        }
        if (lane == 0) {
#pragma unroll
            for (int j = 0; j < STEP; ++j) {
                red[warp][j]        = s8[j];
                red[warp][j + STEP] = q8[j];
            }
        }
        __syncthreads();
        if (warp == 0) {
            float v = 0.f;
            if (lane < 16) {
#pragma unroll
                for (int w = 0; w < 8; ++w) v += red[w][lane];
            }
            float vq = __shfl_down_sync(0xffffffffu, v, STEP);
            if (lane < STEP) {
                float mu  = v * (1.f / HID);
                float var = fmaf(vq, 1.f / HID, -mu * mu);
                bcast[0][lane] = mu;
                bcast[1][lane] = rsqrtf(var + 1e-5f);
            }
        }
        __syncthreads();
#pragma unroll
        for (int j = 0; j < STEP; ++j) {
            size_t o = base2 + (size_t)(t0 + j) * H2;
            float mu = bcast[0][j], rstd = bcast[1][j];
            float2 ov;
            ov.x = (h8[j].x - mu) * rstd * gm.x + bt.x + r8[j].x;
            ov.y = (h8[j].y - mu) * rstd * gm.y + bt.y + r8[j].y;
            __stcs(o2g + o, ov);
            if (write_split)
                __stcs(a2g + o, __floats2half2_rn(ov.x, ov.y));
        }
    }
}

// ============================================================================
extern "C" void kernel_launch(void* const* d_in, const int* in_sizes, int n_in,
                              void* d_out, int out_size)
{
    const float* x     = (const float*)d_in[0];
    const float* h0    = (const float*)d_in[1];
    const float* Wz    = (const float*)d_in[2];
    const float* bz    = (const float*)d_in[3];
    const float* Wh    = (const float*)d_in[4];
    const float* bh    = (const float*)d_in[5];
    const float* gamma = (const float*)d_in[6];
    const float* beta  = (const float*)d_in[7];

    float* out_cur = (float*)d_out;                       // (B, T, H)
    float* out_hid = out_cur + (size_t)MTOT * HID;        // (L, B, H)

    conv_w<<<(NLAYERS * HID * HID) / 256, 256>>>(Wz, Wh);
    conv_x<<<(MTOT * HID / 2) / 256, 256>>>(x);

    const float* cur = x;
    for (int i = 0; i < NLAYERS; ++i) {
        gates_gemm<<<dim3(8, MTOT / BM), 256, SMEM_BYTES>>>(
            i, bz + i * HID, bh + i * HID);
        scan_summary<<<BATCH * NC * 2, 128>>>();
        scanB<<<64, 256>>>(h0 + (size_t)i * BATCH * HID,
                           out_hid + (size_t)i * BATCH * HID);
        scan_ln<<<BATCH * NC, 256>>>(cur, gamma + i * HID, beta + i * HID,
                                     out_cur, (i < NLAYERS - 1) ? 1 : 0);
        cur = out_cur;
    }
}

// round 11
// speedup vs baseline: 2.0658x; 1.0194x over previous
#include <cuda_runtime.h>
#include <cuda_bf16.h>
#include <cuda_fp16.h>
#include <cstdint>

#define NLAYERS 4
#define HID 512
#define BATCH 32
#define SEQ 2048
#define MTOT (BATCH*SEQ)          // 65536
#define NC 64                     // scan chunks
#define TC (SEQ/NC)               // 32 steps per chunk
#define STEP 8                    // timesteps per reduction round in scan_ln
#define H2 (HID/2)                // 256 channel-pairs per row

// ---------------- GEMM tiling ----------------
#define BM 128
#define BN 128
#define BK 32
#define LDA 40                    // BK + 8 pad (row = 80B)
#define LDB 136                   // BN + 8 pad (row = 272B)
#define STAGE_EL (BM*LDA + BK*LDB)                // 9472 fp16
#define SMEM_BYTES (2*STAGE_EL*2)                 // 37888 bytes

// ---------------- scratch ----------------
__device__ __half g_kh[(size_t)MTOT * HID];       // z-gate pre-activation (fp16)
__device__ __half g_ph[(size_t)MTOT * HID];       // h~ pre-activation (fp16)
__device__ __half g_Af[(size_t)MTOT * HID];       // activations / residual (fp16)
__device__ __half g_Wf[(size_t)NLAYERS * 2 * HID * HID];  // weights (fp16)
__device__ float g_cA[BATCH * NC * HID];
__device__ float g_cB[BATCH * NC * HID];
__device__ float g_hin[BATCH * NC * HID];

// ---------------- helpers ----------------
__device__ __forceinline__ uint32_t saddr(const void* p) {
    return (uint32_t)__cvta_generic_to_shared(p);
}
__device__ __forceinline__ void cpasync16(void* smem, const void* g) {
    asm volatile("cp.async.cg.shared.global [%0], [%1], 16;"
                 :: "r"(saddr(smem)), "l"(g));
}
__device__ __forceinline__ void cp_commit() {
    asm volatile("cp.async.commit_group;");
}
__device__ __forceinline__ void cp_wait0() {
    asm volatile("cp.async.wait_group 0;");
}
__device__ __forceinline__ void ldm_x4(uint32_t* r, uint32_t a) {
    asm volatile("ldmatrix.sync.aligned.m8n8.x4.shared.b16 {%0,%1,%2,%3}, [%4];"
                 : "=r"(r[0]), "=r"(r[1]), "=r"(r[2]), "=r"(r[3]) : "r"(a));
}
__device__ __forceinline__ void ldm_x2t(uint32_t* r, uint32_t a) {
    asm volatile("ldmatrix.sync.aligned.m8n8.x2.trans.shared.b16 {%0,%1}, [%2];"
                 : "=r"(r[0]), "=r"(r[1]) : "r"(a));
}
__device__ __forceinline__ void mma16816(float* c, const uint32_t* a, const uint32_t* b) {
    asm volatile(
        "mma.sync.aligned.m16n8k16.row.col.f32.f16.f16.f32 "
        "{%0,%1,%2,%3}, {%4,%5,%6,%7}, {%8,%9}, {%0,%1,%2,%3};"
        : "+f"(c[0]), "+f"(c[1]), "+f"(c[2]), "+f"(c[3])
        : "r"(a[0]), "r"(a[1]), "r"(a[2]), "r"(a[3]), "r"(b[0]), "r"(b[1]));
}

// ============================================================================
// One-shot conversion kernels
// ============================================================================
__global__ void __launch_bounds__(256) conv_w(const float* __restrict__ Wz,
                                              const float* __restrict__ Wh) {
    size_t i = (size_t)blockIdx.x * 256 + threadIdx.x;    // over 4*512*512
    size_t l = i >> 18, r = i & ((1u << 18) - 1);
    g_Wf[((l * 2 + 0) << 18) + r] = __float2half_rn(Wz[i]);
    g_Wf[((l * 2 + 1) << 18) + r] = __float2half_rn(Wh[i]);
}

__global__ void __launch_bounds__(256) conv_x(const float* __restrict__ x) {
    size_t i = (size_t)blockIdx.x * 256 + threadIdx.x;    // over MTOT*HID/2
    float2 v = ((const float2*)x)[i];
    ((__half2*)g_Af)[i] = __floats2half2_rn(v.x, v.y);
}

// ============================================================================
// Fused dual GEMM, single-pass fp16 operands, fp32 accumulate, fp16 output.
// grid = (8, MTOT/128): blockIdx.x = {4 n-tiles} x {z / h}.
// ============================================================================
__global__ void __launch_bounds__(256, 2) gates_gemm(
    int layer, const float* __restrict__ bz, const float* __restrict__ bh)
{
    extern __shared__ __align__(16) char smem_raw[];
    __half* s = (__half*)smem_raw;

    const int tid  = threadIdx.x;
    const int lane = tid & 31;
    const int warp = tid >> 5;
    const int wm   = warp >> 2;
    const int wn   = warp & 3;
    const int zsel = blockIdx.x >> 2;
    const int colBase = (blockIdx.x & 3) * BN;
    const size_t rowBase = (size_t)blockIdx.y * BM;

    const __half* W_   = g_Wf + (((size_t)layer * 2 + zsel) << 18);
    const float* bias  = zsel ? bh : bz;
    __half*      Out   = zsel ? g_ph : g_kh;

    auto issue = [&](int kt, int st) {
        __half* sb = s + st * STAGE_EL;
        {   // A: 512 chunks of 16B (4 per row), 2 per thread
#pragma unroll
            for (int j = 0; j < 2; ++j) {
                int i = tid + 256 * j;
                int row = i >> 2, ch = i & 3;
                const __half* gsrc = g_Af + (rowBase + row) * HID + kt * BK + ch * 8;
                cpasync16(sb + row * LDA + ch * 8, gsrc);
            }
        }
        {   // B: 512 chunks of 16B (16 per row), 2 per thread
#pragma unroll
            for (int j = 0; j < 2; ++j) {
                int i = tid + 256 * j;
                int row = i >> 4, ch = i & 15;
                const __half* gsrc = W_ + (size_t)(kt * BK + row) * HID + colBase + ch * 8;
                cpasync16(sb + BM * LDA + row * LDB + ch * 8, gsrc);
            }
        }
        cp_commit();
    };

    float acc[4][4][4];
#pragma unroll
    for (int mt = 0; mt < 4; ++mt)
#pragma unroll
        for (int nt = 0; nt < 4; ++nt)
#pragma unroll
            for (int r = 0; r < 4; ++r) acc[mt][nt][r] = 0.f;

    auto comp = [&](int st) {
        const __half* sA = s + st * STAGE_EL;
        const __half* sB = sA + BM * LDA;
#pragma unroll
        for (int ks = 0; ks < 2; ++ks) {
            uint32_t B[4][2];
#pragma unroll
            for (int nt = 0; nt < 4; ++nt) {
                int br = ks * 16 + (lane & 15);
                int bc = wn * 32 + nt * 8;
                ldm_x2t(B[nt], saddr(sB + br * LDB + bc));
            }
#pragma unroll
            for (int mt = 0; mt < 4; ++mt) {
                uint32_t A[4];
                int ar = wm * 64 + mt * 16 + (lane & 15);
                int ac = ks * 16 + ((lane >> 4) << 3);
                ldm_x4(A, saddr(sA + ar * LDA + ac));
#pragma unroll
                for (int nt = 0; nt < 4; ++nt)
                    mma16816(acc[mt][nt], A, B[nt]);
            }
        }
    };

    issue(0, 0);
    const int KI = HID / BK;    // 16
    for (int kt = 0; kt < KI; ++kt) {
        int st = kt & 1;
        cp_wait0();
        __syncthreads();
        if (kt + 1 < KI) issue(kt + 1, st ^ 1);
        comp(st);
    }

#pragma unroll
    for (int mt = 0; mt < 4; ++mt) {
        size_t r0 = rowBase + wm * 64 + mt * 16 + (lane >> 2);
#pragma unroll
        for (int nt = 0; nt < 4; ++nt) {
            int cb = colBase + wn * 32 + nt * 8 + ((lane & 3) << 1);
            float2 bs = *(const float2*)(bias + cb);
            *(__half2*)(Out + r0 * HID + cb) =
                __floats2half2_rn(acc[mt][nt][0] + bs.x, acc[mt][nt][1] + bs.y);
            *(__half2*)(Out + (r0 + 8) * HID + cb) =
                __floats2half2_rn(acc[mt][nt][2] + bs.x, acc[mt][nt][3] + bs.y);
        }
    }
}

// ============================================================================
// Scan summary pass: chunk-level (P, S) only; fp16 k/p, 2 channels/thread.
// grid = BATCH*NC*2 = 4096 blocks x 128 threads, TC=32 steps each.
// ============================================================================
__global__ void __launch_bounds__(128) scan_summary() {
    int b     = blockIdx.x >> 7;                  // NC*2 = 128 blocks per batch
    int chunk = (blockIdx.x >> 1) & (NC - 1);
    int c2    = (blockIdx.x & 1) * 128 + threadIdx.x;   // half2 index 0..255
    size_t base = ((size_t)b * SEQ + chunk * TC) * H2 + c2;

    const __half2* k2g = (const __half2*)g_kh;
    const __half2* p2g = (const __half2*)g_ph;

    float2 S = make_float2(0.f, 0.f), P = make_float2(1.f, 1.f);
#pragma unroll 8
    for (int t = 0; t < TC; ++t) {
        size_t o = base + (size_t)t * H2;
        float2 kv = __half22float2(__ldcs(k2g + o));
        float2 pv = __half22float2(__ldcs(p2g + o));
        float ekx = __expf(-kv.x), eky = __expf(-kv.y);
        float zx  = __fdividef(1.f, 1.f + ekx);
        float zy  = __fdividef(1.f, 1.f + eky);
        float ax  = ekx * zx, ay = eky * zy;
        float gpx = (pv.x >= 0.f) ? (pv.x + 0.5f)
                                  : __fdividef(1.f, 1.f + __expf(-pv.x));
        float gpy = (pv.y >= 0.f) ? (pv.y + 0.5f)
                                  : __fdividef(1.f, 1.f + __expf(-pv.y));
        S.x = fmaf(ax, S.x, zx * gpx);
        S.y = fmaf(ay, S.y, zy * gpy);
        P.x *= ax;
        P.y *= ay;
    }
    ((float2*)g_cA)[(b * NC + chunk) * H2 + c2] = P;
    ((float2*)g_cB)[(b * NC + chunk) * H2 + c2] = S;
}

// ============================================================================
// Chain chunk summaries; emit per-chunk h_in and final hiddens.
// ============================================================================
__global__ void __launch_bounds__(256) scanB(const float* __restrict__ h0l,
                                             float* __restrict__ hid_out) {
    int idx = blockIdx.x * 256 + threadIdx.x;   // 16384
    int b = idx >> 9, c = idx & 511;
    float x0 = h0l[b * HID + c];
    float h = (x0 >= 0.f) ? (x0 + 0.5f)
                          : __fdividef(1.f, 1.f + __expf(-x0));
#pragma unroll
    for (int j = 0; j < NC; ++j) {
        g_hin[(b * NC + j) * HID + c] = h;
        h = fmaf(g_cA[(b * NC + j) * HID + c], h, g_cB[(b * NC + j) * HID + c]);
    }
    hid_out[b * HID + c] = h;
}

// ============================================================================
// Fused scan + LayerNorm + residual.
// Residual source: fp32 x (layer 0) or fp16 g_Af in place (layers 1..3) —
// the g_Af pointer is taken INSIDE device code (device symbol address).
// Every residual element is read strictly before the same thread rewrites it.
// Output: layers 0-2 write only fp16 g_Af; layer 3 writes only fp32 d_out.
// ============================================================================
__global__ void __launch_bounds__(256, 2) scan_ln(const float* __restrict__ residf,
                                                  const float* __restrict__ gamma,
                                                  const float* __restrict__ beta,
                                                  float* __restrict__ outp,
                                                  int resid_is_fp16,
                                                  int write_out,
                                                  int write_split) {
    __shared__ float red[8][16];      // [warp][8 x s, 8 x s2]
    __shared__ float bcast[2][STEP];  // [mu | rstd][step]
    int b = blockIdx.x >> 6, chunk = blockIdx.x & (NC - 1);
    int c2 = threadIdx.x, lane = c2 & 31, warp = c2 >> 5;

    float2 h   = ((const float2*)g_hin)[(b * NC + chunk) * H2 + c2];
    float2 gm  = __ldg((const float2*)gamma + c2);
    float2 bt  = __ldg((const float2*)beta + c2);
    size_t base2 = ((size_t)b * SEQ + chunk * TC) * H2 + c2;   // pair index

    const __half2* k2g   = (const __half2*)g_kh;
    const __half2* p2g   = (const __half2*)g_ph;
    const __half2* residh = (const __half2*)g_Af;   // device-side symbol address
    const float2*  r2g   = (const float2*)residf;
    float2*        o2g   = (float2*)outp;
    __half2*       a2g   = (__half2*)g_Af;

    __half2 kc[STEP], pc[STEP];
    float2  rc[STEP];
#pragma unroll
    for (int j = 0; j < STEP; ++j) {              // prologue loads (round 0)
        size_t o = base2 + (size_t)j * H2;
        kc[j] = __ldcs(k2g + o);
        pc[j] = __ldcs(p2g + o);
        rc[j] = resid_is_fp16 ? __half22float2(__ldcs(residh + o))
                              : __ldcs(r2g + o);
    }

#pragma unroll
    for (int t0 = 0; t0 < TC; t0 += STEP) {
        float2 h8[STEP];
        float s8[STEP], q8[STEP];
#pragma unroll
        for (int j = 0; j < STEP; ++j) {          // 8-step h chain (2 ch)
            float2 kv = __half22float2(kc[j]);
            float2 pv = __half22float2(pc[j]);
            float ekx = __expf(-kv.x), eky = __expf(-kv.y);
            float zx  = __fdividef(1.f, 1.f + ekx);
            float zy  = __fdividef(1.f, 1.f + eky);
            float ax  = ekx * zx, ay = eky * zy;
            float gpx = (pv.x >= 0.f) ? (pv.x + 0.5f)
                                      : __fdividef(1.f, 1.f + __expf(-pv.x));
            float gpy = (pv.y >= 0.f) ? (pv.y + 0.5f)
                                      : __fdividef(1.f, 1.f + __expf(-pv.y));
            h.x = fmaf(ax, h.x, zx * gpx);
            h.y = fmaf(ay, h.y, zy * gpy);
            h8[j] = h;
            s8[j] = h.x + h.y;
            q8[j] = h.x * h.x + h.y * h.y;
        }
        float2 r8[STEP];
#pragma unroll
        for (int j = 0; j < STEP; ++j) r8[j] = rc[j];

        // prefetch next round while the reduction runs
        if (t0 + STEP < TC) {
#pragma unroll
            for (int j = 0; j < STEP; ++j) {
                size_t o = base2 + (size_t)(t0 + STEP + j) * H2;
                kc[j] = __ldcs(k2g + o);
                pc[j] = __ldcs(p2g + o);
                rc[j] = resid_is_fp16 ? __half22float2(__ldcs(residh + o))
                                      : __ldcs(r2g + o);
            }
        }

        // warp butterfly: 16 independent reductions, full ILP
#pragma unroll
        for (int off = 16; off; off >>= 1) {
#pragma unroll
            for (int j = 0; j < STEP; ++j) {
                s8[j] += __shfl_xor_sync(0xffffffffu, s8[j], off);
                q8[j] += __shfl_xor_sync(0xffffffffu, q8[j], off);
            }
        }
        if (lane == 0) {
#pragma unroll
            for (int j = 0; j < STEP; ++j) {
                red[warp][j]        = s8[j];
                red[warp][j + STEP] = q8[j];
            }
        }
        __syncthreads();
        if (warp == 0) {
            float v = 0.f;
            if (lane < 16) {
#pragma unroll
                for (int w = 0; w < 8; ++w) v += red[w][lane];
            }
            float vq = __shfl_down_sync(0xffffffffu, v, STEP);
            if (lane < STEP) {
                float mu  = v * (1.f / HID);
                float var = fmaf(vq, 1.f / HID, -mu * mu);
                bcast[0][lane] = mu;
                bcast[1][lane] = rsqrtf(var + 1e-5f);
            }
        }
        __syncthreads();
#pragma unroll
        for (int j = 0; j < STEP; ++j) {
            size_t o = base2 + (size_t)(t0 + j) * H2;
            float mu = bcast[0][j], rstd = bcast[1][j];
            float2 ov;
            ov.x = (h8[j].x - mu) * rstd * gm.x + bt.x + r8[j].x;
            ov.y = (h8[j].y - mu) * rstd * gm.y + bt.y + r8[j].y;
            if (write_out)
                __stcs(o2g + o, ov);
            if (write_split)
                __stcs(a2g + o, __floats2half2_rn(ov.x, ov.y));
        }
    }
}

// ============================================================================
extern "C" void kernel_launch(void* const* d_in, const int* in_sizes, int n_in,
                              void* d_out, int out_size)
{
    const float* x     = (const float*)d_in[0];
    const float* h0    = (const float*)d_in[1];
    const float* Wz    = (const float*)d_in[2];
    const float* bz    = (const float*)d_in[3];
    const float* Wh    = (const float*)d_in[4];
    const float* bh    = (const float*)d_in[5];
    const float* gamma = (const float*)d_in[6];
    const float* beta  = (const float*)d_in[7];

    float* out_cur = (float*)d_out;                       // (B, T, H)
    float* out_hid = out_cur + (size_t)MTOT * HID;        // (L, B, H)

    conv_w<<<(NLAYERS * HID * HID) / 256, 256>>>(Wz, Wh);
    conv_x<<<(MTOT * HID / 2) / 256, 256>>>(x);

    for (int i = 0; i < NLAYERS; ++i) {
        gates_gemm<<<dim3(8, MTOT / BM), 256, SMEM_BYTES>>>(
            i, bz + i * HID, bh + i * HID);
        scan_summary<<<BATCH * NC * 2, 128>>>();
        scanB<<<64, 256>>>(h0 + (size_t)i * BATCH * HID,
                           out_hid + (size_t)i * BATCH * HID);
        int last = (i == NLAYERS - 1);
        scan_ln<<<BATCH * NC, 256>>>(
            x,                                  // fp32 resid (layer 0 only)
            gamma + i * HID, beta + i * HID,
            out_cur,
            /*resid_is_fp16=*/(i > 0) ? 1 : 0,
            /*write_out=*/last,
            /*write_split=*/last ? 0 : 1);
    }
}

// round 12
// speedup vs baseline: 2.1563x; 1.0438x over previous
#include <cuda_runtime.h>
#include <cuda_bf16.h>
#include <cuda_fp16.h>
#include <cstdint>

#define NLAYERS 4
#define HID 512
#define BATCH 32
#define SEQ 2048
#define MTOT (BATCH*SEQ)          // 65536
#define NC 64                     // scan chunks
#define TC (SEQ/NC)               // 32 steps per chunk
#define STEP 8                    // timesteps per reduction round in scan_ln
#define H2 (HID/2)                // 256 channel-pairs per row
#define H4 (HID/4)                // 128 channel-quads per row

// ---------------- GEMM tiling ----------------
#define BM 128
#define BN 128
#define BK 32
#define LDA 40                    // BK + 8 pad (row = 80B)
#define LDB 136                   // BN + 8 pad (row = 272B)
#define STAGE_EL (BM*LDA + BK*LDB)                // 9472 fp16
#define SMEM_BYTES (2*STAGE_EL*2)                 // 37888 bytes

// ---------------- scratch ----------------
__device__ __half g_ah[(size_t)MTOT * HID];       // a = sigmoid(-k)   (fp16)
__device__ __half g_gp[(size_t)MTOT * HID];       // gp = g(p)         (fp16)
__device__ __half g_Af[(size_t)MTOT * HID];       // activations / residual (fp16)
__device__ __half g_Wf[(size_t)NLAYERS * 2 * HID * HID];  // weights (fp16)
__device__ float g_cA[BATCH * NC * HID];
__device__ float g_cB[BATCH * NC * HID];
__device__ float g_hin[BATCH * NC * HID];

// ---------------- helpers ----------------
__device__ __forceinline__ uint32_t saddr(const void* p) {
    return (uint32_t)__cvta_generic_to_shared(p);
}
__device__ __forceinline__ void cpasync16(void* smem, const void* g) {
    asm volatile("cp.async.cg.shared.global [%0], [%1], 16;"
                 :: "r"(saddr(smem)), "l"(g));
}
__device__ __forceinline__ void cp_commit() {
    asm volatile("cp.async.commit_group;");
}
__device__ __forceinline__ void cp_wait0() {
    asm volatile("cp.async.wait_group 0;");
}
__device__ __forceinline__ void ldm_x4(uint32_t* r, uint32_t a) {
    asm volatile("ldmatrix.sync.aligned.m8n8.x4.shared.b16 {%0,%1,%2,%3}, [%4];"
                 : "=r"(r[0]), "=r"(r[1]), "=r"(r[2]), "=r"(r[3]) : "r"(a));
}
__device__ __forceinline__ void ldm_x2t(uint32_t* r, uint32_t a) {
    asm volatile("ldmatrix.sync.aligned.m8n8.x2.trans.shared.b16 {%0,%1}, [%2];"
                 : "=r"(r[0]), "=r"(r[1]) : "r"(a));
}
__device__ __forceinline__ void mma16816(float* c, const uint32_t* a, const uint32_t* b) {
    asm volatile(
        "mma.sync.aligned.m16n8k16.row.col.f32.f16.f16.f32 "
        "{%0,%1,%2,%3}, {%4,%5,%6,%7}, {%8,%9}, {%0,%1,%2,%3};"
        : "+f"(c[0]), "+f"(c[1]), "+f"(c[2]), "+f"(c[3])
        : "r"(a[0]), "r"(a[1]), "r"(a[2]), "r"(a[3]), "r"(b[0]), "r"(b[1]));
}
__device__ __forceinline__ float sig_neg(float v) {     // sigmoid(-v)
    return __fdividef(1.f, 1.f + __expf(v));
}
__device__ __forceinline__ float gfun(float v) {        // minGRU g()
    return (v >= 0.f) ? (v + 0.5f) : __fdividef(1.f, 1.f + __expf(-v));
}

// ============================================================================
// One-shot conversion kernels
// ============================================================================
__global__ void __launch_bounds__(256) conv_w(const float* __restrict__ Wz,
                                              const float* __restrict__ Wh) {
    size_t i = (size_t)blockIdx.x * 256 + threadIdx.x;    // over 4*512*512
    size_t l = i >> 18, r = i & ((1u << 18) - 1);
    g_Wf[((l * 2 + 0) << 18) + r] = __float2half_rn(Wz[i]);
    g_Wf[((l * 2 + 1) << 18) + r] = __float2half_rn(Wh[i]);
}

__global__ void __launch_bounds__(256) conv_x(const float* __restrict__ x) {
    size_t i = (size_t)blockIdx.x * 256 + threadIdx.x;    // over MTOT*HID/2
    float2 v = ((const float2*)x)[i];
    ((__half2*)g_Af)[i] = __floats2half2_rn(v.x, v.y);
}

// ============================================================================
// Fused dual GEMM, fp16 operands, fp32 accumulate.
// Epilogue applies the gate activation: zsel=0 stores a=sigmoid(-(k)),
// zsel=1 stores gp=g(p).  grid = (8, MTOT/128).
// ============================================================================
__global__ void __launch_bounds__(256, 2) gates_gemm(
    int layer, const float* __restrict__ bz, const float* __restrict__ bh)
{
    extern __shared__ __align__(16) char smem_raw[];
    __half* s = (__half*)smem_raw;

    const int tid  = threadIdx.x;
    const int lane = tid & 31;
    const int warp = tid >> 5;
    const int wm   = warp >> 2;
    const int wn   = warp & 3;
    const int zsel = blockIdx.x >> 2;
    const int colBase = (blockIdx.x & 3) * BN;
    const size_t rowBase = (size_t)blockIdx.y * BM;

    const __half* W_   = g_Wf + (((size_t)layer * 2 + zsel) << 18);
    const float* bias  = zsel ? bh : bz;
    __half*      Out   = zsel ? g_gp : g_ah;

    auto issue = [&](int kt, int st) {
        __half* sb = s + st * STAGE_EL;
        {   // A: 512 chunks of 16B (4 per row), 2 per thread
#pragma unroll
            for (int j = 0; j < 2; ++j) {
                int i = tid + 256 * j;
                int row = i >> 2, ch = i & 3;
                const __half* gsrc = g_Af + (rowBase + row) * HID + kt * BK + ch * 8;
                cpasync16(sb + row * LDA + ch * 8, gsrc);
            }
        }
        {   // B: 512 chunks of 16B (16 per row), 2 per thread
#pragma unroll
            for (int j = 0; j < 2; ++j) {
                int i = tid + 256 * j;
                int row = i >> 4, ch = i & 15;
                const __half* gsrc = W_ + (size_t)(kt * BK + row) * HID + colBase + ch * 8;
                cpasync16(sb + BM * LDA + row * LDB + ch * 8, gsrc);
            }
        }
        cp_commit();
    };

    float acc[4][4][4];
#pragma unroll
    for (int mt = 0; mt < 4; ++mt)
#pragma unroll
        for (int nt = 0; nt < 4; ++nt)
#pragma unroll
            for (int r = 0; r < 4; ++r) acc[mt][nt][r] = 0.f;

    auto comp = [&](int st) {
        const __half* sA = s + st * STAGE_EL;
        const __half* sB = sA + BM * LDA;
#pragma unroll
        for (int ks = 0; ks < 2; ++ks) {
            uint32_t B[4][2];
#pragma unroll
            for (int nt = 0; nt < 4; ++nt) {
                int br = ks * 16 + (lane & 15);
                int bc = wn * 32 + nt * 8;
                ldm_x2t(B[nt], saddr(sB + br * LDB + bc));
            }
#pragma unroll
            for (int mt = 0; mt < 4; ++mt) {
                uint32_t A[4];
                int ar = wm * 64 + mt * 16 + (lane & 15);
                int ac = ks * 16 + ((lane >> 4) << 3);
                ldm_x4(A, saddr(sA + ar * LDA + ac));
#pragma unroll
                for (int nt = 0; nt < 4; ++nt)
                    mma16816(acc[mt][nt], A, B[nt]);
            }
        }
    };

    issue(0, 0);
    const int KI = HID / BK;    // 16
    for (int kt = 0; kt < KI; ++kt) {
        int st = kt & 1;
        cp_wait0();
        __syncthreads();
        if (kt + 1 < KI) issue(kt + 1, st ^ 1);
        comp(st);
    }

#pragma unroll
    for (int mt = 0; mt < 4; ++mt) {
        size_t r0 = rowBase + wm * 64 + mt * 16 + (lane >> 2);
#pragma unroll
        for (int nt = 0; nt < 4; ++nt) {
            int cb = colBase + wn * 32 + nt * 8 + ((lane & 3) << 1);
            float2 bs = *(const float2*)(bias + cb);
            float v0 = acc[mt][nt][0] + bs.x, v1 = acc[mt][nt][1] + bs.y;
            float v2 = acc[mt][nt][2] + bs.x, v3 = acc[mt][nt][3] + bs.y;
            if (zsel == 0) {
                v0 = sig_neg(v0); v1 = sig_neg(v1);
                v2 = sig_neg(v2); v3 = sig_neg(v3);
            } else {
                v0 = gfun(v0); v1 = gfun(v1);
                v2 = gfun(v2); v3 = gfun(v3);
            }
            *(__half2*)(Out + r0 * HID + cb)       = __floats2half2_rn(v0, v1);
            *(__half2*)(Out + (r0 + 8) * HID + cb) = __floats2half2_rn(v2, v3);
        }
    }
}

// ============================================================================
// Scan summary pass: chunk (P, S); pure FMA (activations precomputed).
// grid = BATCH*NC = 2048 blocks x 128 threads, 4 channels/thread, TC=32 steps.
// ============================================================================
__global__ void __launch_bounds__(128) scan_summary() {
    int b     = blockIdx.x >> 6;                  // NC = 64
    int chunk = blockIdx.x & (NC - 1);
    int c4    = threadIdx.x;                      // quad index 0..127
    size_t base = ((size_t)(b * SEQ + chunk * TC)) * H4 + c4;

    const uint2* a4g = (const uint2*)g_ah;
    const uint2* g4g = (const uint2*)g_gp;

    float S[4] = {0.f, 0.f, 0.f, 0.f};
    float P[4] = {1.f, 1.f, 1.f, 1.f};
#pragma unroll 8
    for (int t = 0; t < TC; ++t) {
        size_t o = base + (size_t)t * H4;
        uint2 av = __ldcs(a4g + o);
        uint2 gv = __ldcs(g4g + o);
        float2 a01 = __half22float2(*(__half2*)&av.x);
        float2 a23 = __half22float2(*(__half2*)&av.y);
        float2 g01 = __half22float2(*(__half2*)&gv.x);
        float2 g23 = __half22float2(*(__half2*)&gv.y);
        S[0] = fmaf(a01.x, S[0] - g01.x, g01.x);  P[0] *= a01.x;
        S[1] = fmaf(a01.y, S[1] - g01.y, g01.y);  P[1] *= a01.y;
        S[2] = fmaf(a23.x, S[2] - g23.x, g23.x);  P[2] *= a23.x;
        S[3] = fmaf(a23.y, S[3] - g23.y, g23.y);  P[3] *= a23.y;
    }
    ((float4*)g_cA)[(b * NC + chunk) * H4 + c4] = make_float4(P[0], P[1], P[2], P[3]);
    ((float4*)g_cB)[(b * NC + chunk) * H4 + c4] = make_float4(S[0], S[1], S[2], S[3]);
}

// ============================================================================
// Chain chunk summaries; emit per-chunk h_in and final hiddens.
// ============================================================================
__global__ void __launch_bounds__(256) scanB(const float* __restrict__ h0l,
                                             float* __restrict__ hid_out) {
    int idx = blockIdx.x * 256 + threadIdx.x;   // 16384
    int b = idx >> 9, c = idx & 511;
    float x0 = h0l[b * HID + c];
    float h = (x0 >= 0.f) ? (x0 + 0.5f)
                          : __fdividef(1.f, 1.f + __expf(-x0));
#pragma unroll
    for (int j = 0; j < NC; ++j) {
        g_hin[(b * NC + j) * HID + c] = h;
        h = fmaf(g_cA[(b * NC + j) * HID + c], h, g_cB[(b * NC + j) * HID + c]);
    }
    hid_out[b * HID + c] = h;
}

// ============================================================================
// Fused scan + LayerNorm + residual (pure-FMA recurrence).
// Residual source: fp32 x (layer 0) or fp16 g_Af in place (layers 1..3).
// Output: layers 0-2 write only fp16 g_Af; layer 3 writes only fp32 d_out.
// ============================================================================
__global__ void __launch_bounds__(256, 2) scan_ln(const float* __restrict__ residf,
                                                  const float* __restrict__ gamma,
                                                  const float* __restrict__ beta,
                                                  float* __restrict__ outp,
                                                  int resid_is_fp16,
                                                  int write_out,
                                                  int write_split) {
    __shared__ float red[8][16];      // [warp][8 x s, 8 x s2]
    __shared__ float bcast[2][STEP];  // [mu | rstd][step]
    int b = blockIdx.x >> 6, chunk = blockIdx.x & (NC - 1);
    int c2 = threadIdx.x, lane = c2 & 31, warp = c2 >> 5;

    float2 h   = ((const float2*)g_hin)[(b * NC + chunk) * H2 + c2];
    float2 gm  = __ldg((const float2*)gamma + c2);
    float2 bt  = __ldg((const float2*)beta + c2);
    size_t base2 = ((size_t)b * SEQ + chunk * TC) * H2 + c2;   // pair index

    const __half2* a2g    = (const __half2*)g_ah;
    const __half2* gp2g   = (const __half2*)g_gp;
    const __half2* residh = (const __half2*)g_Af;   // device-side symbol address
    const float2*  r2g    = (const float2*)residf;
    float2*        o2g    = (float2*)outp;
    __half2*       af2g   = (__half2*)g_Af;

    __half2 ac[STEP], gc[STEP];
    float2  rc[STEP];
#pragma unroll
    for (int j = 0; j < STEP; ++j) {              // prologue loads (round 0)
        size_t o = base2 + (size_t)j * H2;
        ac[j] = __ldcs(a2g + o);
        gc[j] = __ldcs(gp2g + o);
        rc[j] = resid_is_fp16 ? __half22float2(__ldcs(residh + o))
                              : __ldcs(r2g + o);
    }

#pragma unroll
    for (int t0 = 0; t0 < TC; t0 += STEP) {
        float2 h8[STEP];
        float s8[STEP], q8[STEP];
#pragma unroll
        for (int j = 0; j < STEP; ++j) {          // 8-step h chain (2 ch)
            float2 av = __half22float2(ac[j]);
            float2 gv = __half22float2(gc[j]);
            h.x = fmaf(av.x, h.x - gv.x, gv.x);
            h.y = fmaf(av.y, h.y - gv.y, gv.y);
            h8[j] = h;
            s8[j] = h.x + h.y;
            q8[j] = h.x * h.x + h.y * h.y;
        }
        float2 r8[STEP];
#pragma unroll
        for (int j = 0; j < STEP; ++j) r8[j] = rc[j];

        // prefetch next round while the reduction runs
        if (t0 + STEP < TC) {
#pragma unroll
            for (int j = 0; j < STEP; ++j) {
                size_t o = base2 + (size_t)(t0 + STEP + j) * H2;
                ac[j] = __ldcs(a2g + o);
                gc[j] = __ldcs(gp2g + o);
                rc[j] = resid_is_fp16 ? __half22float2(__ldcs(residh + o))
                                      : __ldcs(r2g + o);
            }
        }

        // warp butterfly: 16 independent reductions, full ILP
#pragma unroll
        for (int off = 16; off; off >>= 1) {
#pragma unroll
            for (int j = 0; j < STEP; ++j) {
                s8[j] += __shfl_xor_sync(0xffffffffu, s8[j], off);
                q8[j] += __shfl_xor_sync(0xffffffffu, q8[j], off);
            }
        }
        if (lane == 0) {
#pragma unroll
            for (int j = 0; j < STEP; ++j) {
                red[warp][j]        = s8[j];
                red[warp][j + STEP] = q8[j];
            }
        }
        __syncthreads();
        if (warp == 0) {
            float v = 0.f;
            if (lane < 16) {
#pragma unroll
                for (int w = 0; w < 8; ++w) v += red[w][lane];
            }
            float vq = __shfl_down_sync(0xffffffffu, v, STEP);
            if (lane < STEP) {
                float mu  = v * (1.f / HID);
                float var = fmaf(vq, 1.f / HID, -mu * mu);
                bcast[0][lane] = mu;
                bcast[1][lane] = rsqrtf(var + 1e-5f);
            }
        }
        __syncthreads();
#pragma unroll
        for (int j = 0; j < STEP; ++j) {
            size_t o = base2 + (size_t)(t0 + j) * H2;
            float mu = bcast[0][j], rstd = bcast[1][j];
            float2 ov;
            ov.x = (h8[j].x - mu) * rstd * gm.x + bt.x + r8[j].x;
            ov.y = (h8[j].y - mu) * rstd * gm.y + bt.y + r8[j].y;
            if (write_out)
                __stcs(o2g + o, ov);
            if (write_split)
                __stcs(af2g + o, __floats2half2_rn(ov.x, ov.y));
        }
    }
}

// ============================================================================
extern "C" void kernel_launch(void* const* d_in, const int* in_sizes, int n_in,
                              void* d_out, int out_size)
{
    const float* x     = (const float*)d_in[0];
    const float* h0    = (const float*)d_in[1];
    const float* Wz    = (const float*)d_in[2];
    const float* bz    = (const float*)d_in[3];
    const float* Wh    = (const float*)d_in[4];
    const float* bh    = (const float*)d_in[5];
    const float* gamma = (const float*)d_in[6];
    const float* beta  = (const float*)d_in[7];

    float* out_cur = (float*)d_out;                       // (B, T, H)
    float* out_hid = out_cur + (size_t)MTOT * HID;        // (L, B, H)

    conv_w<<<(NLAYERS * HID * HID) / 256, 256>>>(Wz, Wh);
    conv_x<<<(MTOT * HID / 2) / 256, 256>>>(x);

    for (int i = 0; i < NLAYERS; ++i) {
        gates_gemm<<<dim3(8, MTOT / BM), 256, SMEM_BYTES>>>(
            i, bz + i * HID, bh + i * HID);
        scan_summary<<<BATCH * NC, 128>>>();
        scanB<<<64, 256>>>(h0 + (size_t)i * BATCH * HID,
                           out_hid + (size_t)i * BATCH * HID);
        int last = (i == NLAYERS - 1);
        scan_ln<<<BATCH * NC, 256>>>(
            x,                                  // fp32 resid (layer 0 only)
            gamma + i * HID, beta + i * HID,
            out_cur,
            /*resid_is_fp16=*/(i > 0) ? 1 : 0,
            /*write_out=*/last,
            /*write_split=*/last ? 0 : 1);
    }
}